// round 1
// baseline (speedup 1.0000x reference)
#include <cuda_runtime.h>

// Problem constants
#define B   2
#define S   2048
#define D   1024
#define H   16
#define HD  64
#define BSZ (B*S)    // 4096 rows for projections
#define BH  (B*H)    // 32 (batch*heads)

// Scratch (static device globals; no runtime allocation)
__device__ float g_q [BH * S * HD];          // (B,H,S,hd) head-major, pre-scaled by 1/sqrt(hd)
__device__ float g_k [BH * S * HD];
__device__ float g_v [BH * S * HD];
__device__ float g_g [BH * S * HD];          // sigmoid gate, head-major
__device__ float g_ao[BSZ * D];              // gated attention output, (B,S,D)
__device__ float g_sc[(size_t)BH * S * S];   // scores -> probs, 1.07 GB

// ---------------------------------------------------------------------------
// Projection GEMM: C(M=4096, N=1024) = A(4096,1024) @ W(1024,1024) + bias
// 128x128 block tile, BK=16, 8x8 per-thread micro tile, 256 threads.
// MODE: 0 = plain row-major store (final output proj)
//       1 = head-major store (k, v)
//       2 = head-major store, scaled by 1/sqrt(hd) (q)
//       3 = sigmoid then head-major store (gate)
// ---------------------------------------------------------------------------
template<int MODE>
__global__ __launch_bounds__(256) void proj_gemm(const float* __restrict__ A,
                                                 const float* __restrict__ W,
                                                 const float* __restrict__ bias,
                                                 float* __restrict__ out)
{
    __shared__ float As[16][128];   // As[k][m] (transposed)
    __shared__ float Ws[16][128];   // Ws[k][n]

    const int tid = threadIdx.x;
    const int bm  = blockIdx.y * 128;
    const int bn  = blockIdx.x * 128;
    const int tm  = (tid >> 4) << 3;       // 0..120 step 8
    const int tn  = (tid & 15) << 3;       // 0..120 step 8
    const int a_r = tid >> 2;              // 0..63
    const int a_c = (tid & 3) << 2;        // 0,4,8,12
    const int w_r = tid >> 5;              // 0..7
    const int w_c = (tid & 31) << 2;       // 0..124

    float acc[8][8] = {};

    for (int k0 = 0; k0 < D; k0 += 16) {
        #pragma unroll
        for (int p = 0; p < 2; ++p) {
            int r = a_r + (p << 6);
            float4 t4 = *reinterpret_cast<const float4*>(A + (size_t)(bm + r) * D + k0 + a_c);
            As[a_c + 0][r] = t4.x; As[a_c + 1][r] = t4.y;
            As[a_c + 2][r] = t4.z; As[a_c + 3][r] = t4.w;
        }
        #pragma unroll
        for (int p = 0; p < 2; ++p) {
            int r = w_r + (p << 3);
            *reinterpret_cast<float4*>(&Ws[r][w_c]) =
                *reinterpret_cast<const float4*>(W + (size_t)(k0 + r) * D + bn + w_c);
        }
        __syncthreads();
        #pragma unroll
        for (int kk = 0; kk < 16; ++kk) {
            float ar[8], wr[8];
            #pragma unroll
            for (int i = 0; i < 8; ++i) ar[i] = As[kk][tm + i];
            #pragma unroll
            for (int j = 0; j < 8; ++j) wr[j] = Ws[kk][tn + j];
            #pragma unroll
            for (int i = 0; i < 8; ++i)
                #pragma unroll
                for (int j = 0; j < 8; ++j)
                    acc[i][j] = fmaf(ar[i], wr[j], acc[i][j]);
        }
        __syncthreads();
    }

    #pragma unroll
    for (int i = 0; i < 8; ++i) {
        int m = bm + tm + i;
        int b = m >> 11, s = m & 2047;
        #pragma unroll
        for (int j = 0; j < 8; ++j) {
            int n = bn + tn + j;
            float val = acc[i][j] + bias[n];
            if (MODE == 0) {
                out[(size_t)m * D + n] = val;
            } else {
                int h = n >> 6, d = n & 63;
                if (MODE == 2) val *= 0.125f;                       // 1/sqrt(64)
                if (MODE == 3) val = 1.0f / (1.0f + __expf(-val));  // sigmoid
                out[(((size_t)(b * H + h)) * S + s) * HD + d] = val;
            }
        }
    }
}

// ---------------------------------------------------------------------------
// Scores = (q/scale) @ k^T + attn_mask, with key padding mask.
// Per (b,h): M=N=2048, K=64. NT GEMM, 128x128 tile, BK=16.
// ---------------------------------------------------------------------------
__global__ __launch_bounds__(256) void qk_scores(const float* __restrict__ qm,
                                                 const float* __restrict__ km,
                                                 const float* __restrict__ amask,
                                                 const unsigned char* __restrict__ kpm,
                                                 float* __restrict__ sc)
{
    const int bh = blockIdx.z;
    const float* Aq = qm + (size_t)bh * S * HD;
    const float* Bk = km + (size_t)bh * S * HD;
    const int bm = blockIdx.y * 128;   // query tile
    const int bn = blockIdx.x * 128;   // key tile

    __shared__ float Qs[16][128];
    __shared__ float Ks[16][128];

    const int tid = threadIdx.x;
    const int tm  = (tid >> 4) << 3;
    const int tn  = (tid & 15) << 3;
    const int lr  = tid >> 2;          // 0..63
    const int lc  = (tid & 3) << 2;    // 0,4,8,12

    float acc[8][8] = {};

    for (int k0 = 0; k0 < HD; k0 += 16) {
        #pragma unroll
        for (int p = 0; p < 2; ++p) {
            int r = lr + (p << 6);
            float4 a = *reinterpret_cast<const float4*>(Aq + (size_t)(bm + r) * HD + k0 + lc);
            Qs[lc + 0][r] = a.x; Qs[lc + 1][r] = a.y; Qs[lc + 2][r] = a.z; Qs[lc + 3][r] = a.w;
            float4 b = *reinterpret_cast<const float4*>(Bk + (size_t)(bn + r) * HD + k0 + lc);
            Ks[lc + 0][r] = b.x; Ks[lc + 1][r] = b.y; Ks[lc + 2][r] = b.z; Ks[lc + 3][r] = b.w;
        }
        __syncthreads();
        #pragma unroll
        for (int kk = 0; kk < 16; ++kk) {
            float qr[8], kr[8];
            #pragma unroll
            for (int i = 0; i < 8; ++i) qr[i] = Qs[kk][tm + i];
            #pragma unroll
            for (int j = 0; j < 8; ++j) kr[j] = Ks[kk][tn + j];
            #pragma unroll
            for (int i = 0; i < 8; ++i)
                #pragma unroll
                for (int j = 0; j < 8; ++j)
                    acc[i][j] = fmaf(qr[i], kr[j], acc[i][j]);
        }
        __syncthreads();
    }

    const int b = bh >> 4;
    #pragma unroll
    for (int i = 0; i < 8; ++i) {
        int qi = bm + tm + i;
        #pragma unroll
        for (int j = 0; j < 8; ++j) {
            int kj = bn + tn + j;
            float v = acc[i][j] + amask[qi * S + kj];
            if (kpm[b * S + kj]) v = -1e30f;
            sc[((size_t)bh * S + qi) * S + kj] = v;
        }
    }
}

// ---------------------------------------------------------------------------
// Row softmax over last dim (len 2048). One block per row; row lives in regs.
// ---------------------------------------------------------------------------
__global__ __launch_bounds__(256) void softmax_rows(float* __restrict__ sc)
{
    float* p = sc + (size_t)blockIdx.x * S;
    const int t = threadIdx.x;
    float v[8];
    float mx = -3.0e38f;
    #pragma unroll
    for (int i = 0; i < 8; ++i) { v[i] = p[t + (i << 8)]; mx = fmaxf(mx, v[i]); }
    #pragma unroll
    for (int o = 16; o; o >>= 1) mx = fmaxf(mx, __shfl_xor_sync(0xffffffffu, mx, o));
    __shared__ float smax[8], ssum[8];
    if ((t & 31) == 0) smax[t >> 5] = mx;
    __syncthreads();
    float rmax = smax[0];
    #pragma unroll
    for (int i = 1; i < 8; ++i) rmax = fmaxf(rmax, smax[i]);
    float s = 0.0f;
    #pragma unroll
    for (int i = 0; i < 8; ++i) { v[i] = __expf(v[i] - rmax); s += v[i]; }
    #pragma unroll
    for (int o = 16; o; o >>= 1) s += __shfl_xor_sync(0xffffffffu, s, o);
    if ((t & 31) == 0) ssum[t >> 5] = s;
    __syncthreads();
    float tot = 0.0f;
    #pragma unroll
    for (int i = 0; i < 8; ++i) tot += ssum[i];
    float inv = 1.0f / tot;
    #pragma unroll
    for (int i = 0; i < 8; ++i) p[t + (i << 8)] = v[i] * inv;
}

// ---------------------------------------------------------------------------
// avg_attn[b,i,j] = mean over heads of probs[b,h,i,j]
// ---------------------------------------------------------------------------
__global__ __launch_bounds__(256) void avg_heads(const float* __restrict__ sc,
                                                 float* __restrict__ avg)
{
    const int bi = blockIdx.x;                // b*S + i
    const int b  = bi >> 11, i = bi & 2047;
    const int t  = threadIdx.x;
    #pragma unroll
    for (int jb = 0; jb < 8; ++jb) {
        int j = t + (jb << 8);
        float a = 0.0f;
        #pragma unroll
        for (int h = 0; h < H; ++h)
            a += sc[(((size_t)(b * H + h)) * S + i) * S + j];
        avg[(size_t)bi * S + j] = a * (1.0f / H);
    }
}

// ---------------------------------------------------------------------------
// attn_out = probs @ v, gated, written back to (B,S,D) layout.
// Per (b,h): M=2048, N=64, K=2048. Tile 128x64, BK=16, 8x4 micro tile.
// ---------------------------------------------------------------------------
__global__ __launch_bounds__(256) void pv_gate(const float* __restrict__ sc,
                                               const float* __restrict__ vm,
                                               const float* __restrict__ gm,
                                               float* __restrict__ ao)
{
    const int bh = blockIdx.z;
    const int bm = blockIdx.y * 128;            // s-tile
    const float* A  = sc + (size_t)bh * S * S;
    const float* Vv = vm + (size_t)bh * S * HD;

    __shared__ float As[16][128];
    __shared__ float Vs[16][64];

    const int tid = threadIdx.x;
    const int tm  = (tid >> 4) << 3;            // 0..120
    const int tn  = (tid & 15) << 2;            // 0..60
    const int ar_ = tid >> 2;                   // 0..63
    const int ac  = (tid & 3) << 2;             // 0,4,8,12
    const int vr  = tid >> 4;                   // 0..15
    const int vc  = (tid & 15) << 2;            // 0..60

    float acc[8][4] = {};

    for (int k0 = 0; k0 < S; k0 += 16) {
        #pragma unroll
        for (int p = 0; p < 2; ++p) {
            int r = ar_ + (p << 6);
            float4 a = *reinterpret_cast<const float4*>(A + (size_t)(bm + r) * S + k0 + ac);
            As[ac + 0][r] = a.x; As[ac + 1][r] = a.y; As[ac + 2][r] = a.z; As[ac + 3][r] = a.w;
        }
        *reinterpret_cast<float4*>(&Vs[vr][vc]) =
            *reinterpret_cast<const float4*>(Vv + (size_t)(k0 + vr) * HD + vc);
        __syncthreads();
        #pragma unroll
        for (int kk = 0; kk < 16; ++kk) {
            float ar[8], vv[4];
            #pragma unroll
            for (int i = 0; i < 8; ++i) ar[i] = As[kk][tm + i];
            #pragma unroll
            for (int j = 0; j < 4; ++j) vv[j] = Vs[kk][tn + j];
            #pragma unroll
            for (int i = 0; i < 8; ++i)
                #pragma unroll
                for (int j = 0; j < 4; ++j)
                    acc[i][j] = fmaf(ar[i], vv[j], acc[i][j]);
        }
        __syncthreads();
    }

    const int b = bh >> 4, h = bh & 15;
    #pragma unroll
    for (int i = 0; i < 8; ++i) {
        int s = bm + tm + i;
        #pragma unroll
        for (int j = 0; j < 4; ++j) {
            int d = tn + j;
            float gate = gm[((size_t)bh * S + s) * HD + d];
            ao[((size_t)(b * S + s)) * D + h * HD + d] = acc[i][j] * gate;
        }
    }
}

// ---------------------------------------------------------------------------
extern "C" void kernel_launch(void* const* d_in, const int* in_sizes, int n_in,
                              void* d_out, int out_size)
{
    const float*         x     = (const float*)d_in[0];
    const float*         amask = (const float*)d_in[1];
    const unsigned char* kpm   = (const unsigned char*)d_in[2];
    const float* Wq = (const float*)d_in[3];  const float* bq = (const float*)d_in[4];
    const float* Wk = (const float*)d_in[5];  const float* bk = (const float*)d_in[6];
    const float* Wv = (const float*)d_in[7];  const float* bv = (const float*)d_in[8];
    const float* Wg = (const float*)d_in[9];  const float* bg = (const float*)d_in[10];
    const float* Wo = (const float*)d_in[11]; const float* bo = (const float*)d_in[12];

    float* out = (float*)d_out;               // [0, B*S*D): output; then avg_attn

    float *q, *k, *v, *g, *ao, *sc;
    cudaGetSymbolAddress((void**)&q,  g_q);
    cudaGetSymbolAddress((void**)&k,  g_k);
    cudaGetSymbolAddress((void**)&v,  g_v);
    cudaGetSymbolAddress((void**)&g,  g_g);
    cudaGetSymbolAddress((void**)&ao, g_ao);
    cudaGetSymbolAddress((void**)&sc, g_sc);

    dim3 pth(256);
    dim3 pgr(D / 128, BSZ / 128);             // (8, 32)

    proj_gemm<2><<<pgr, pth>>>(x, Wq, bq, q); // q, pre-scaled
    proj_gemm<1><<<pgr, pth>>>(x, Wk, bk, k);
    proj_gemm<1><<<pgr, pth>>>(x, Wv, bv, v);
    proj_gemm<3><<<pgr, pth>>>(x, Wg, bg, g); // sigmoid gate

    qk_scores<<<dim3(S / 128, S / 128, BH), 256>>>(q, k, amask, kpm, sc);
    softmax_rows<<<BH * S, 256>>>(sc);
    avg_heads<<<BSZ, 256>>>(sc, out + (size_t)BSZ * D);
    pv_gate<<<dim3(1, S / 128, BH), 256>>>(sc, v, g, ao);

    proj_gemm<0><<<pgr, pth>>>(ao, Wo, bo, out);
}

// round 5
// speedup vs baseline: 2.2490x; 2.2490x over previous
#include <cuda_runtime.h>
#include <cuda_bf16.h>
#include <cstdint>

#define Bb   2
#define Ss   2048
#define Dd   1024
#define Hh   16
#define HDd  64
#define BHh  32
#define BSZ  4096

// ------------------------------ scratch ------------------------------------
__device__ __nv_bfloat16 g_xh[BSZ * Dd], g_xl[BSZ * Dd];
__device__ __nv_bfloat16 g_wth[5 * Dd * Dd], g_wtl[5 * Dd * Dd];       // W^T hi/lo, [n][k]
__device__ __nv_bfloat16 g_qh[BHh * Ss * HDd], g_ql[BHh * Ss * HDd];
__device__ __nv_bfloat16 g_kh[BHh * Ss * HDd], g_kl[BHh * Ss * HDd];
__device__ __nv_bfloat16 g_vth[BHh * HDd * Ss], g_vtl[BHh * HDd * Ss]; // v^T [bh][d][s]
__device__ float         g_gate[BHh * Ss * HDd];
__device__ float         g_sc[(size_t)BHh * Ss * Ss];                  // scores fp32
__device__ __nv_bfloat16 g_ph[(size_t)BHh * Ss * Ss];                  // probs hi
__device__ __nv_bfloat16 g_pl[(size_t)BHh * Ss * Ss];                  // probs lo
__device__ __nv_bfloat16 g_aoh[BSZ * Dd], g_aol[BSZ * Dd];

// --------------------------- helpers ---------------------------------------
__device__ __forceinline__ uint32_t smem_u32(const void* p) {
    uint32_t a;
    asm("{ .reg .u64 t; cvta.to.shared.u64 t, %1; cvt.u32.u64 %0, t; }" : "=r"(a) : "l"(p));
    return a;
}
#define SWZ128(o) ((o) ^ (((o) >> 3) & 0x70))

__device__ __forceinline__ void ldsm4(uint32_t r[4], uint32_t addr) {
    asm volatile("ldmatrix.sync.aligned.m8n8.x4.shared.b16 {%0,%1,%2,%3}, [%4];"
                 : "=r"(r[0]), "=r"(r[1]), "=r"(r[2]), "=r"(r[3]) : "r"(addr));
}
__device__ __forceinline__ void mma16816(float c[4], const uint32_t a[4], const uint32_t b[2]) {
    asm volatile("mma.sync.aligned.m16n8k16.row.col.f32.bf16.bf16.f32 "
                 "{%0,%1,%2,%3}, {%4,%5,%6,%7}, {%8,%9}, {%0,%1,%2,%3};"
                 : "+f"(c[0]), "+f"(c[1]), "+f"(c[2]), "+f"(c[3])
                 : "r"(a[0]), "r"(a[1]), "r"(a[2]), "r"(a[3]), "r"(b[0]), "r"(b[1]));
}
__device__ __forceinline__ void split2(float x, __nv_bfloat16& h, __nv_bfloat16& l) {
    h = __float2bfloat16(x);
    l = __float2bfloat16(x - __bfloat162float(h));
}

// ---------------------------------------------------------------------------
// One BK=64 k-chunk of a warp-tile GEMM with bf16 hi/lo 3-term splitting.
// smem tiles: row-major, 128 bytes (64 bf16) per row, SW128 swizzled.
// A tiles: (block M rows) x 64; B tiles: (block N rows) x 64 (i.e. B^T, K-contig).
// Warp computes WM*16 rows x WN*8 cols starting at (m0, n0) within the tile.
// ---------------------------------------------------------------------------
template<int WM, int WN>
__device__ __forceinline__ void warp_mma_iter(
    float (&C)[WM][WN][4],
    uint32_t aAh, uint32_t aAl, uint32_t aBh, uint32_t aBl,
    int m0, int n0, int lane)
{
    uint32_t Bh[WN][2][4], Bl[WN][2][4];
    #pragma unroll
    for (int n = 0; n < WN; ++n)
        #pragma unroll
        for (int hf = 0; hf < 2; ++hf) {
            uint32_t off = SWZ128((uint32_t)((n0 + n * 8 + (lane & 7)) * 128 + hf * 64 + ((lane >> 3) << 4)));
            ldsm4(Bh[n][hf], aBh + off);
            ldsm4(Bl[n][hf], aBl + off);
        }
    #pragma unroll
    for (int ks = 0; ks < 4; ++ks) {
        uint32_t Ah[WM][4], Al[WM][4];
        const int t = lane >> 3, r = lane & 7;
        #pragma unroll
        for (int m = 0; m < WM; ++m) {
            uint32_t off = SWZ128((uint32_t)((m0 + m * 16 + r + ((t & 1) << 3)) * 128 + ks * 32 + ((t >> 1) << 4)));
            ldsm4(Ah[m], aAh + off);
            ldsm4(Al[m], aAl + off);
        }
        #pragma unroll
        for (int m = 0; m < WM; ++m)
            #pragma unroll
            for (int n = 0; n < WN; ++n) {
                const uint32_t* bh = &Bh[n][ks >> 1][(ks & 1) << 1];
                const uint32_t* bl = &Bl[n][ks >> 1][(ks & 1) << 1];
                mma16816(C[m][n], Ah[m], bh);
                mma16816(C[m][n], Ah[m], bl);
                mma16816(C[m][n], Al[m], bh);
            }
    }
}

// -------------------- conversion kernels -----------------------------------
__global__ __launch_bounds__(256) void split_f32(const float* __restrict__ in,
                                                 __nv_bfloat16* __restrict__ hi,
                                                 __nv_bfloat16* __restrict__ lo, int n) {
    for (int i = blockIdx.x * 256 + threadIdx.x; i < n; i += gridDim.x * 256)
        split2(in[i], hi[i], lo[i]);
}

// W [K=1024, N=1024] row-major  ->  Wt[n][k] hi/lo
__global__ __launch_bounds__(256) void wt_split(const float* __restrict__ W,
                                                __nv_bfloat16* __restrict__ th,
                                                __nv_bfloat16* __restrict__ tl) {
    __shared__ float t[32][33];
    const int tx = threadIdx.x, ty = threadIdx.y;
    const int n0 = blockIdx.x * 32, k0 = blockIdx.y * 32;
    #pragma unroll
    for (int i = 0; i < 4; ++i)
        t[ty + 8 * i][tx] = W[(size_t)(k0 + ty + 8 * i) * Dd + n0 + tx];
    __syncthreads();
    #pragma unroll
    for (int i = 0; i < 4; ++i) {
        float v = t[tx][ty + 8 * i];
        size_t o = (size_t)(n0 + ty + 8 * i) * Dd + k0 + tx;
        split2(v, th[o], tl[o]);
    }
}

// ---------------------------------------------------------------------------
// Projection GEMM: C(4096,1024) = A(4096,1024) @ Wt^T + bias, bf16x3 HMMA.
// Block 128x128, BK=64, 8 warps (2m x 4n), warp tile 64x32.
// MODE: 0 fp32 row-major; 1 k hi/lo head-major; 2 q hi/lo head-major *0.125;
//       3 gate sigmoid fp32 head-major; 4 v hi/lo transposed [bh][d][s]
// ---------------------------------------------------------------------------
template<int MODE>
__device__ __forceinline__ void proj_store1(int m, int n, float val,
    float* outf, __nv_bfloat16* oh, __nv_bfloat16* ol)
{
    if (MODE == 0) { outf[(size_t)m * Dd + n] = val; return; }
    const int bb = m >> 11, ss = m & 2047, h = n >> 6, d = n & 63;
    if (MODE == 2) val *= 0.125f;
    if (MODE == 3) {
        outf[((size_t)(bb * Hh + h) * Ss + ss) * HDd + d] = 1.0f / (1.0f + __expf(-val));
        return;
    }
    size_t o;
    if (MODE == 4) o = ((size_t)(bb * Hh + h) * HDd + d) * Ss + ss;
    else           o = ((size_t)(bb * Hh + h) * Ss + ss) * HDd + d;
    split2(val, oh[o], ol[o]);
}

template<int MODE>
__global__ __launch_bounds__(256) void proj_mma(
    const __nv_bfloat16* __restrict__ Ah, const __nv_bfloat16* __restrict__ Al,
    const __nv_bfloat16* __restrict__ Bh, const __nv_bfloat16* __restrict__ Bl,
    const float* __restrict__ bias,
    float* __restrict__ outf, __nv_bfloat16* __restrict__ oh, __nv_bfloat16* __restrict__ ol)
{
    extern __shared__ char smem[];
    char* sAh = smem;
    char* sAl = smem + 16384;
    char* sBh = smem + 32768;
    char* sBl = smem + 49152;
    const uint32_t aAh = smem_u32(sAh), aAl = smem_u32(sAl);
    const uint32_t aBh = smem_u32(sBh), aBl = smem_u32(sBl);

    const int tid = threadIdx.x, lane = tid & 31, wid = tid >> 5;
    const int bm = blockIdx.y * 128, bn = blockIdx.x * 128;
    const int wm0 = (wid >> 2) * 64, wn0 = (wid & 3) * 32;

    float C[4][4][4] = {};

    for (int k0 = 0; k0 < Dd; k0 += 64) {
        #pragma unroll
        for (int p = 0; p < 4; ++p) {
            int u = tid + (p << 8);
            int r = u >> 3, c = u & 7;
            uint32_t so = SWZ128((uint32_t)(r * 128 + c * 16));
            size_t ga = (size_t)(bm + r) * Dd + k0 + c * 8;
            size_t gb = (size_t)(bn + r) * Dd + k0 + c * 8;
            *(uint4*)(sAh + so) = *(const uint4*)(Ah + ga);
            *(uint4*)(sAl + so) = *(const uint4*)(Al + ga);
            *(uint4*)(sBh + so) = *(const uint4*)(Bh + gb);
            *(uint4*)(sBl + so) = *(const uint4*)(Bl + gb);
        }
        __syncthreads();
        warp_mma_iter<4, 4>(C, aAh, aAl, aBh, aBl, wm0, wn0, lane);
        __syncthreads();
    }

    const int m0 = bm + wm0, n0 = bn + wn0;
    #pragma unroll
    for (int m = 0; m < 4; ++m)
        #pragma unroll
        for (int n = 0; n < 4; ++n) {
            int r0 = m0 + m * 16 + (lane >> 2);
            int cc = n0 + n * 8 + ((lane & 3) << 1);
            float b0 = bias[cc], b1 = bias[cc + 1];
            proj_store1<MODE>(r0,     cc,     C[m][n][0] + b0, outf, oh, ol);
            proj_store1<MODE>(r0,     cc + 1, C[m][n][1] + b1, outf, oh, ol);
            proj_store1<MODE>(r0 + 8, cc,     C[m][n][2] + b0, outf, oh, ol);
            proj_store1<MODE>(r0 + 8, cc + 1, C[m][n][3] + b1, outf, oh, ol);
        }
}

// ---------------------------------------------------------------------------
// Scores: per (b,h) q(2048,64) @ k(2048,64)^T + mask. K=64 (one chunk).
// ---------------------------------------------------------------------------
__global__ __launch_bounds__(256) void qk_mma(
    const __nv_bfloat16* __restrict__ qh, const __nv_bfloat16* __restrict__ ql,
    const __nv_bfloat16* __restrict__ kh, const __nv_bfloat16* __restrict__ kl,
    const float* __restrict__ amask, const unsigned char* __restrict__ kpm,
    float* __restrict__ sc)
{
    extern __shared__ char smem[];
    char* sAh = smem;
    char* sAl = smem + 16384;
    char* sBh = smem + 32768;
    char* sBl = smem + 49152;
    const uint32_t aAh = smem_u32(sAh), aAl = smem_u32(sAl);
    const uint32_t aBh = smem_u32(sBh), aBl = smem_u32(sBl);

    const int tid = threadIdx.x, lane = tid & 31, wid = tid >> 5;
    const int bn = blockIdx.x * 128, bm = blockIdx.y * 128, bh = blockIdx.z;
    const int bb = bh >> 4;

    const __nv_bfloat16* Qh = qh + (size_t)bh * Ss * HDd;
    const __nv_bfloat16* Ql = ql + (size_t)bh * Ss * HDd;
    const __nv_bfloat16* Kh = kh + (size_t)bh * Ss * HDd;
    const __nv_bfloat16* Kl = kl + (size_t)bh * Ss * HDd;

    #pragma unroll
    for (int p = 0; p < 4; ++p) {
        int u = tid + (p << 8);
        int r = u >> 3, c = u & 7;
        uint32_t so = SWZ128((uint32_t)(r * 128 + c * 16));
        size_t gq = (size_t)(bm + r) * HDd + c * 8;
        size_t gk = (size_t)(bn + r) * HDd + c * 8;
        *(uint4*)(sAh + so) = *(const uint4*)(Qh + gq);
        *(uint4*)(sAl + so) = *(const uint4*)(Ql + gq);
        *(uint4*)(sBh + so) = *(const uint4*)(Kh + gk);
        *(uint4*)(sBl + so) = *(const uint4*)(Kl + gk);
    }
    __syncthreads();

    float C[4][4][4] = {};
    warp_mma_iter<4, 4>(C, aAh, aAl, aBh, aBl, (wid >> 2) * 64, (wid & 3) * 32, lane);

    const int m0 = bm + (wid >> 2) * 64, n0 = bn + (wid & 3) * 32;
    #pragma unroll
    for (int m = 0; m < 4; ++m)
        #pragma unroll
        for (int n = 0; n < 4; ++n) {
            int qi0 = m0 + m * 16 + (lane >> 2);
            int kj  = n0 + n * 8 + ((lane & 3) << 1);
            bool p0 = kpm[bb * Ss + kj], p1 = kpm[bb * Ss + kj + 1];
            #pragma unroll
            for (int hh = 0; hh < 2; ++hh) {
                int qi = qi0 + hh * 8;
                float2 mk = *(const float2*)(amask + (size_t)qi * Ss + kj);
                float2 v;
                v.x = C[m][n][hh * 2 + 0] + mk.x;
                v.y = C[m][n][hh * 2 + 1] + mk.y;
                if (p0) v.x = -1e30f;
                if (p1) v.y = -1e30f;
                *(float2*)(sc + ((size_t)bh * Ss + qi) * Ss + kj) = v;
            }
        }
}

// ---------------------------------------------------------------------------
// Fused softmax over heads + head average.  One block per (b, i) row.
// ---------------------------------------------------------------------------
__global__ __launch_bounds__(256) void softmax_avg(const float* __restrict__ sc,
                                                   __nv_bfloat16* __restrict__ ph,
                                                   __nv_bfloat16* __restrict__ pl,
                                                   float* __restrict__ avg)
{
    const int bi = blockIdx.x;
    const int b = bi >> 11, i = bi & 2047;
    const int t = threadIdx.x, lane = t & 31, w = t >> 5;
    __shared__ float sred[8];
    float acc[8] = {0, 0, 0, 0, 0, 0, 0, 0};

    for (int h = 0; h < Hh; ++h) {
        const size_t ro = ((size_t)(b * Hh + h) * Ss + i) * Ss;
        const float* row = sc + ro;
        float v[8];
        float mx = -3.0e38f;
        #pragma unroll
        for (int j = 0; j < 8; ++j) { v[j] = row[t + (j << 8)]; mx = fmaxf(mx, v[j]); }
        #pragma unroll
        for (int o = 16; o; o >>= 1) mx = fmaxf(mx, __shfl_xor_sync(0xffffffffu, mx, o));
        if (lane == 0) sred[w] = mx;
        __syncthreads();
        float rmax = sred[0];
        #pragma unroll
        for (int j = 1; j < 8; ++j) rmax = fmaxf(rmax, sred[j]);
        __syncthreads();
        float s = 0.0f;
        #pragma unroll
        for (int j = 0; j < 8; ++j) { v[j] = __expf(v[j] - rmax); s += v[j]; }
        #pragma unroll
        for (int o = 16; o; o >>= 1) s += __shfl_xor_sync(0xffffffffu, s, o);
        if (lane == 0) sred[w] = s;
        __syncthreads();
        float tot = 0.0f;
        #pragma unroll
        for (int j = 0; j < 8; ++j) tot += sred[j];
        __syncthreads();
        float inv = 1.0f / tot;
        #pragma unroll
        for (int j = 0; j < 8; ++j) {
            float p = v[j] * inv;
            acc[j] += p;
            split2(p, ph[ro + t + (j << 8)], pl[ro + t + (j << 8)]);
        }
    }
    #pragma unroll
    for (int j = 0; j < 8; ++j)
        avg[(size_t)bi * Ss + t + (j << 8)] = acc[j] * (1.0f / Hh);
}

// ---------------------------------------------------------------------------
// PV: per (b,h) probs(2048,2048) @ v(2048,64); gate; emit ao bf16 hi/lo.
// Block 128x64, BK=64, 8 warps (4m x 2n), warp tile 32x32.
// ---------------------------------------------------------------------------
__global__ __launch_bounds__(256) void pv_mma(
    const __nv_bfloat16* __restrict__ phm, const __nv_bfloat16* __restrict__ plm,
    const __nv_bfloat16* __restrict__ vth, const __nv_bfloat16* __restrict__ vtl,
    const float* __restrict__ gate,
    __nv_bfloat16* __restrict__ aoh, __nv_bfloat16* __restrict__ aol)
{
    extern __shared__ char smem[];
    char* sPh = smem;
    char* sPl = smem + 16384;
    char* sVh = smem + 32768;
    char* sVl = smem + 40960;
    const uint32_t aPh = smem_u32(sPh), aPl = smem_u32(sPl);
    const uint32_t aVh = smem_u32(sVh), aVl = smem_u32(sVl);

    const int tid = threadIdx.x, lane = tid & 31, wid = tid >> 5;
    const int bm = blockIdx.x * 128, bh = blockIdx.y;
    const int bb = bh >> 4, hh = bh & 15;

    const __nv_bfloat16* Ph = phm + (size_t)bh * Ss * Ss;
    const __nv_bfloat16* Pl = plm + (size_t)bh * Ss * Ss;
    const __nv_bfloat16* Vh = vth + (size_t)bh * HDd * Ss;
    const __nv_bfloat16* Vl = vtl + (size_t)bh * HDd * Ss;

    float C[2][4][4] = {};
    const int wm0 = (wid >> 1) * 32, wn0 = (wid & 1) * 32;

    for (int k0 = 0; k0 < Ss; k0 += 64) {
        #pragma unroll
        for (int p = 0; p < 4; ++p) {
            int u = tid + (p << 8);
            int r = u >> 3, c = u & 7;
            uint32_t so = SWZ128((uint32_t)(r * 128 + c * 16));
            size_t gp = (size_t)(bm + r) * Ss + k0 + c * 8;
            *(uint4*)(sPh + so) = *(const uint4*)(Ph + gp);
            *(uint4*)(sPl + so) = *(const uint4*)(Pl + gp);
        }
        #pragma unroll
        for (int p = 0; p < 2; ++p) {
            int u = tid + (p << 8);
            int r = u >> 3, c = u & 7;
            uint32_t so = SWZ128((uint32_t)(r * 128 + c * 16));
            size_t gv = (size_t)r * Ss + k0 + c * 8;
            *(uint4*)(sVh + so) = *(const uint4*)(Vh + gv);
            *(uint4*)(sVl + so) = *(const uint4*)(Vl + gv);
        }
        __syncthreads();
        warp_mma_iter<2, 4>(C, aPh, aPl, aVh, aVl, wm0, wn0, lane);
        __syncthreads();
    }

    #pragma unroll
    for (int m = 0; m < 2; ++m)
        #pragma unroll
        for (int n = 0; n < 4; ++n) {
            int s0 = bm + wm0 + m * 16 + (lane >> 2);
            int d  = wn0 + n * 8 + ((lane & 3) << 1);
            #pragma unroll
            for (int q = 0; q < 2; ++q) {
                int s = s0 + q * 8;
                const float* grow = gate + ((size_t)bh * Ss + s) * HDd;
                __nv_bfloat16* doh = aoh + (size_t)(bb * Ss + s) * Dd + hh * HDd;
                __nv_bfloat16* dol = aol + (size_t)(bb * Ss + s) * Dd + hh * HDd;
                float v0 = C[m][n][q * 2 + 0] * grow[d];
                float v1 = C[m][n][q * 2 + 1] * grow[d + 1];
                split2(v0, doh[d], dol[d]);
                split2(v1, doh[d + 1], dol[d + 1]);
            }
        }
}

// ---------------------------------------------------------------------------
extern "C" void kernel_launch(void* const* d_in, const int* in_sizes, int n_in,
                              void* d_out, int out_size)
{
    const float*         x     = (const float*)d_in[0];
    const float*         amask = (const float*)d_in[1];
    const unsigned char* kpm   = (const unsigned char*)d_in[2];
    const float* Wq = (const float*)d_in[3];  const float* bq = (const float*)d_in[4];
    const float* Wk = (const float*)d_in[5];  const float* bk = (const float*)d_in[6];
    const float* Wv = (const float*)d_in[7];  const float* bv = (const float*)d_in[8];
    const float* Wg = (const float*)d_in[9];  const float* bg = (const float*)d_in[10];
    const float* Wo = (const float*)d_in[11]; const float* bo = (const float*)d_in[12];

    float* out = (float*)d_out;

    __nv_bfloat16 *xh, *xl, *wth, *wtl, *qh, *ql, *kh, *kl, *vth, *vtl, *phm, *plm, *aoh, *aol;
    float *gate, *sc;
    cudaGetSymbolAddress((void**)&xh,  g_xh);  cudaGetSymbolAddress((void**)&xl,  g_xl);
    cudaGetSymbolAddress((void**)&wth, g_wth); cudaGetSymbolAddress((void**)&wtl, g_wtl);
    cudaGetSymbolAddress((void**)&qh,  g_qh);  cudaGetSymbolAddress((void**)&ql,  g_ql);
    cudaGetSymbolAddress((void**)&kh,  g_kh);  cudaGetSymbolAddress((void**)&kl,  g_kl);
    cudaGetSymbolAddress((void**)&vth, g_vth); cudaGetSymbolAddress((void**)&vtl, g_vtl);
    cudaGetSymbolAddress((void**)&gate, g_gate);
    cudaGetSymbolAddress((void**)&sc,  g_sc);
    cudaGetSymbolAddress((void**)&phm, g_ph);  cudaGetSymbolAddress((void**)&plm, g_pl);
    cudaGetSymbolAddress((void**)&aoh, g_aoh); cudaGetSymbolAddress((void**)&aol, g_aol);

    const int SM_BIG = 65536;   // proj / qk: 4 x 16 KB tiles
    const int SM_PV  = 49152;   // pv: 2 x 16 KB + 2 x 8 KB
    cudaFuncSetAttribute(proj_mma<0>, cudaFuncAttributeMaxDynamicSharedMemorySize, SM_BIG);
    cudaFuncSetAttribute(proj_mma<1>, cudaFuncAttributeMaxDynamicSharedMemorySize, SM_BIG);
    cudaFuncSetAttribute(proj_mma<2>, cudaFuncAttributeMaxDynamicSharedMemorySize, SM_BIG);
    cudaFuncSetAttribute(proj_mma<3>, cudaFuncAttributeMaxDynamicSharedMemorySize, SM_BIG);
    cudaFuncSetAttribute(proj_mma<4>, cudaFuncAttributeMaxDynamicSharedMemorySize, SM_BIG);
    cudaFuncSetAttribute(qk_mma,      cudaFuncAttributeMaxDynamicSharedMemorySize, SM_BIG);
    cudaFuncSetAttribute(pv_mma,      cudaFuncAttributeMaxDynamicSharedMemorySize, SM_PV);

    // 1. conversions
    split_f32<<<2048, 256>>>(x, xh, xl, BSZ * Dd);
    wt_split<<<dim3(32, 32), dim3(32, 8)>>>(Wq, wth + 0 * Dd * Dd, wtl + 0 * Dd * Dd);
    wt_split<<<dim3(32, 32), dim3(32, 8)>>>(Wk, wth + 1 * Dd * Dd, wtl + 1 * Dd * Dd);
    wt_split<<<dim3(32, 32), dim3(32, 8)>>>(Wv, wth + 2 * Dd * Dd, wtl + 2 * Dd * Dd);
    wt_split<<<dim3(32, 32), dim3(32, 8)>>>(Wg, wth + 3 * Dd * Dd, wtl + 3 * Dd * Dd);
    wt_split<<<dim3(32, 32), dim3(32, 8)>>>(Wo, wth + 4 * Dd * Dd, wtl + 4 * Dd * Dd);

    // 2. projections
    dim3 pg(8, 32);
    proj_mma<2><<<pg, 256, SM_BIG>>>(xh, xl, wth + 0 * Dd * Dd, wtl + 0 * Dd * Dd, bq, nullptr, qh, ql);
    proj_mma<1><<<pg, 256, SM_BIG>>>(xh, xl, wth + 1 * Dd * Dd, wtl + 1 * Dd * Dd, bk, nullptr, kh, kl);
    proj_mma<4><<<pg, 256, SM_BIG>>>(xh, xl, wth + 2 * Dd * Dd, wtl + 2 * Dd * Dd, bv, nullptr, vth, vtl);
    proj_mma<3><<<pg, 256, SM_BIG>>>(xh, xl, wth + 3 * Dd * Dd, wtl + 3 * Dd * Dd, bg, gate, nullptr, nullptr);

    // 3. attention
    qk_mma<<<dim3(16, 16, 32), 256, SM_BIG>>>(qh, ql, kh, kl, amask, kpm, sc);
    softmax_avg<<<BSZ, 256>>>(sc, phm, plm, out + (size_t)BSZ * Dd);
    pv_mma<<<dim3(16, 32), 256, SM_PV>>>(phm, plm, vth, vtl, gate, aoh, aol);

    // 4. output projection
    proj_mma<0><<<pg, 256, SM_BIG>>>(aoh, aol, wth + 4 * Dd * Dd, wtl + 4 * Dd * Dd, bo, out, nullptr, nullptr);
}

// round 9
// speedup vs baseline: 2.9258x; 1.3009x over previous
#include <cuda_runtime.h>
#include <cuda_fp16.h>
#include <cstdint>

#define Bb   2
#define Ss   2048
#define Dd   1024
#define Hh   16
#define HDd  64
#define BHh  32
#define BSZ  4096

// ------------------------------ scratch ------------------------------------
__device__ __half g_xh[BSZ * Dd], g_xl[BSZ * Dd];          // x dual fp16
__device__ __half g_wq[Dd * Dd], g_wk[Dd * Dd], g_wg[Dd * Dd];       // W^T single
__device__ __half g_wvh[Dd * Dd], g_wvl[Dd * Dd];                    // Wv^T dual
__device__ __half g_woh[Dd * Dd], g_wol[Dd * Dd];                    // Wo^T dual
__device__ __half g_q[BHh * Ss * HDd], g_k[BHh * Ss * HDd];          // single, head-major
__device__ __half g_vth[BHh * HDd * Ss], g_vtl[BHh * HDd * Ss];      // v^T dual [bh][d][s]
__device__ float  g_gate[BHh * Ss * HDd];
__device__ float  g_sc[(size_t)BHh * Ss * Ss];                       // scores fp32
__device__ __half g_p[(size_t)BHh * Ss * Ss];                        // probs single fp16
__device__ __half g_aoh[BSZ * Dd], g_aol[BSZ * Dd];                  // ao dual

// --------------------------- helpers ---------------------------------------
__device__ __forceinline__ uint32_t smem_u32(const void* p) {
    uint32_t a;
    asm("{ .reg .u64 t; cvta.to.shared.u64 t, %1; cvt.u32.u64 %0, t; }" : "=r"(a) : "l"(p));
    return a;
}
#define SWZ128(o) ((o) ^ (((o) >> 3) & 0x70))

__device__ __forceinline__ void ldsm4(uint32_t r[4], uint32_t addr) {
    asm volatile("ldmatrix.sync.aligned.m8n8.x4.shared.b16 {%0,%1,%2,%3}, [%4];"
                 : "=r"(r[0]), "=r"(r[1]), "=r"(r[2]), "=r"(r[3]) : "r"(addr));
}
__device__ __forceinline__ void mma16816(float c[4], const uint32_t a[4], const uint32_t b[2]) {
    asm volatile("mma.sync.aligned.m16n8k16.row.col.f32.f16.f16.f32 "
                 "{%0,%1,%2,%3}, {%4,%5,%6,%7}, {%8,%9}, {%0,%1,%2,%3};"
                 : "+f"(c[0]), "+f"(c[1]), "+f"(c[2]), "+f"(c[3])
                 : "r"(a[0]), "r"(a[1]), "r"(a[2]), "r"(a[3]), "r"(b[0]), "r"(b[1]));
}
__device__ __forceinline__ void split2h(float x, __half& h, __half& l) {
    h = __float2half_rn(x);
    l = __float2half_rn(x - __half2float(h));
}

// B-fragment loader: WN x (2 halves of k64) x4regs from a tile at (n0 rows)
#define LOAD_BFRAG(dst, abase) \
    _Pragma("unroll") \
    for (int n = 0; n < WN; ++n) \
        _Pragma("unroll") \
        for (int hf = 0; hf < 2; ++hf) { \
            uint32_t off = SWZ128((uint32_t)((n0 + n * 8 + (lane & 7)) * 128 + hf * 64 + ((lane >> 3) << 4))); \
            ldsm4((dst)[n][hf], (abase) + off); \
        }

#define AFRAG_OFF(m) \
    SWZ128((uint32_t)((m0 + (m) * 16 + (lane & 7) + (((lane >> 3) & 1) << 3)) * 128 + ks * 32 + ((lane >> 4) << 4)))

// 1 term: C += A*B
template<int WM, int WN>
__device__ __forceinline__ void warp_mma_1(
    float (&C)[WM][WN][4], uint32_t aA, uint32_t aB, int m0, int n0, int lane)
{
    uint32_t Bf[WN][2][4];
    LOAD_BFRAG(Bf, aB)
    #pragma unroll
    for (int ks = 0; ks < 4; ++ks) {
        uint32_t Af[WM][4];
        #pragma unroll
        for (int m = 0; m < WM; ++m) ldsm4(Af[m], aA + AFRAG_OFF(m));
        #pragma unroll
        for (int m = 0; m < WM; ++m)
            #pragma unroll
            for (int n = 0; n < WN; ++n)
                mma16816(C[m][n], Af[m], &Bf[n][ks >> 1][(ks & 1) << 1]);
    }
}

// 2 terms sharing B: C += A0*B + A1*B
template<int WM, int WN>
__device__ __forceinline__ void warp_mma_2A1B(
    float (&C)[WM][WN][4], uint32_t aA0, uint32_t aA1, uint32_t aB, int m0, int n0, int lane)
{
    uint32_t Bf[WN][2][4];
    LOAD_BFRAG(Bf, aB)
    #pragma unroll
    for (int ks = 0; ks < 4; ++ks) {
        uint32_t A0[WM][4], A1[WM][4];
        #pragma unroll
        for (int m = 0; m < WM; ++m) { ldsm4(A0[m], aA0 + AFRAG_OFF(m)); ldsm4(A1[m], aA1 + AFRAG_OFF(m)); }
        #pragma unroll
        for (int m = 0; m < WM; ++m)
            #pragma unroll
            for (int n = 0; n < WN; ++n) {
                const uint32_t* b = &Bf[n][ks >> 1][(ks & 1) << 1];
                mma16816(C[m][n], A0[m], b);
                mma16816(C[m][n], A1[m], b);
            }
    }
}

// 2 terms sharing A: C += A*B0 + A*B1
template<int WM, int WN>
__device__ __forceinline__ void warp_mma_1A2B(
    float (&C)[WM][WN][4], uint32_t aA, uint32_t aB0, uint32_t aB1, int m0, int n0, int lane)
{
    uint32_t B0[WN][2][4], B1[WN][2][4];
    LOAD_BFRAG(B0, aB0)
    LOAD_BFRAG(B1, aB1)
    #pragma unroll
    for (int ks = 0; ks < 4; ++ks) {
        uint32_t Af[WM][4];
        #pragma unroll
        for (int m = 0; m < WM; ++m) ldsm4(Af[m], aA + AFRAG_OFF(m));
        #pragma unroll
        for (int m = 0; m < WM; ++m)
            #pragma unroll
            for (int n = 0; n < WN; ++n) {
                mma16816(C[m][n], Af[m], &B0[n][ks >> 1][(ks & 1) << 1]);
                mma16816(C[m][n], Af[m], &B1[n][ks >> 1][(ks & 1) << 1]);
            }
    }
}

// 3 terms: C += Ah*Bh + Ah*Bl + Al*Bh
template<int WM, int WN>
__device__ __forceinline__ void warp_mma_3(
    float (&C)[WM][WN][4], uint32_t aAh, uint32_t aAl, uint32_t aBh, uint32_t aBl,
    int m0, int n0, int lane)
{
    uint32_t Bh[WN][2][4], Bl[WN][2][4];
    LOAD_BFRAG(Bh, aBh)
    LOAD_BFRAG(Bl, aBl)
    #pragma unroll
    for (int ks = 0; ks < 4; ++ks) {
        uint32_t Ah[WM][4], Al[WM][4];
        #pragma unroll
        for (int m = 0; m < WM; ++m) { ldsm4(Ah[m], aAh + AFRAG_OFF(m)); ldsm4(Al[m], aAl + AFRAG_OFF(m)); }
        #pragma unroll
        for (int m = 0; m < WM; ++m)
            #pragma unroll
            for (int n = 0; n < WN; ++n) {
                const uint32_t* bh = &Bh[n][ks >> 1][(ks & 1) << 1];
                const uint32_t* bl = &Bl[n][ks >> 1][(ks & 1) << 1];
                mma16816(C[m][n], Ah[m], bh);
                mma16816(C[m][n], Ah[m], bl);
                mma16816(C[m][n], Al[m], bh);
            }
    }
}

// -------------------- conversion kernels -----------------------------------
__global__ __launch_bounds__(256) void split_f16(const float* __restrict__ in,
                                                 __half* __restrict__ hi,
                                                 __half* __restrict__ lo, int n) {
    for (int i = blockIdx.x * 256 + threadIdx.x; i < n; i += gridDim.x * 256)
        split2h(in[i], hi[i], lo[i]);
}

// W [K,N] row-major -> Wt[n][k], single fp16
__global__ __launch_bounds__(256) void wt_1(const float* __restrict__ W, __half* __restrict__ t1) {
    __shared__ float t[32][33];
    const int tx = threadIdx.x, ty = threadIdx.y;
    const int n0 = blockIdx.x * 32, k0 = blockIdx.y * 32;
    #pragma unroll
    for (int i = 0; i < 4; ++i)
        t[ty + 8 * i][tx] = W[(size_t)(k0 + ty + 8 * i) * Dd + n0 + tx];
    __syncthreads();
    #pragma unroll
    for (int i = 0; i < 4; ++i)
        t1[(size_t)(n0 + ty + 8 * i) * Dd + k0 + tx] = __float2half_rn(t[tx][ty + 8 * i]);
}

// W -> Wt dual fp16
__global__ __launch_bounds__(256) void wt_2(const float* __restrict__ W,
                                            __half* __restrict__ th, __half* __restrict__ tl) {
    __shared__ float t[32][33];
    const int tx = threadIdx.x, ty = threadIdx.y;
    const int n0 = blockIdx.x * 32, k0 = blockIdx.y * 32;
    #pragma unroll
    for (int i = 0; i < 4; ++i)
        t[ty + 8 * i][tx] = W[(size_t)(k0 + ty + 8 * i) * Dd + n0 + tx];
    __syncthreads();
    #pragma unroll
    for (int i = 0; i < 4; ++i) {
        size_t o = (size_t)(n0 + ty + 8 * i) * Dd + k0 + tx;
        split2h(t[tx][ty + 8 * i], th[o], tl[o]);
    }
}

// ---------------------------------------------------------------------------
// proj2: C(4096,1024) = (xh+xl) @ W^T + bias, 2 terms.
// MODE: 1 k single head-major; 2 q single head-major *0.125; 3 gate sigmoid fp32
// ---------------------------------------------------------------------------
template<int MODE>
__global__ __launch_bounds__(256) void proj2_mma(
    const __half* __restrict__ Ah, const __half* __restrict__ Al,
    const __half* __restrict__ Bw, const float* __restrict__ bias,
    float* __restrict__ outf, __half* __restrict__ oh)
{
    extern __shared__ char smem[];
    char* sAh = smem;
    char* sAl = smem + 16384;
    char* sBw = smem + 32768;
    const uint32_t aAh = smem_u32(sAh), aAl = smem_u32(sAl), aBw = smem_u32(sBw);

    const int tid = threadIdx.x, lane = tid & 31, wid = tid >> 5;
    const int bm = blockIdx.y * 128, bn = blockIdx.x * 128;
    const int wm0 = (wid >> 2) * 64, wn0 = (wid & 3) * 32;

    float C[4][4][4] = {};

    for (int k0 = 0; k0 < Dd; k0 += 64) {
        #pragma unroll
        for (int p = 0; p < 4; ++p) {
            int u = tid + (p << 8);
            int r = u >> 3, c = u & 7;
            uint32_t so = SWZ128((uint32_t)(r * 128 + c * 16));
            size_t ga = (size_t)(bm + r) * Dd + k0 + c * 8;
            size_t gb = (size_t)(bn + r) * Dd + k0 + c * 8;
            *(uint4*)(sAh + so) = *(const uint4*)(Ah + ga);
            *(uint4*)(sAl + so) = *(const uint4*)(Al + ga);
            *(uint4*)(sBw + so) = *(const uint4*)(Bw + gb);
        }
        __syncthreads();
        warp_mma_2A1B<4, 4>(C, aAh, aAl, aBw, wm0, wn0, lane);
        __syncthreads();
    }

    const int m0 = bm + wm0, n0 = bn + wn0;
    #pragma unroll
    for (int m = 0; m < 4; ++m)
        #pragma unroll
        for (int n = 0; n < 4; ++n) {
            #pragma unroll
            for (int e = 0; e < 4; ++e) {
                int mm = m0 + m * 16 + (lane >> 2) + ((e >> 1) << 3);
                int nn = n0 + n * 8 + ((lane & 3) << 1) + (e & 1);
                float val = C[m][n][e] + bias[nn];
                const int bb = mm >> 11, ss = mm & 2047, h = nn >> 6, d = nn & 63;
                size_t o = ((size_t)(bb * Hh + h) * Ss + ss) * HDd + d;
                if (MODE == 2) oh[o] = __float2half_rn(val * 0.125f);
                else if (MODE == 1) oh[o] = __float2half_rn(val);
                else outf[o] = 1.0f / (1.0f + __expf(-val));
            }
        }
}

// ---------------------------------------------------------------------------
// proj3: C = (Ah+Al) @ (Bh+Bl)^T + bias, 3 terms.
// MODE: 0 fp32 row-major out; 4 v dual transposed [bh][d][s]
// ---------------------------------------------------------------------------
template<int MODE>
__global__ __launch_bounds__(256) void proj3_mma(
    const __half* __restrict__ Ah, const __half* __restrict__ Al,
    const __half* __restrict__ Bh, const __half* __restrict__ Bl,
    const float* __restrict__ bias,
    float* __restrict__ outf, __half* __restrict__ oh, __half* __restrict__ ol)
{
    extern __shared__ char smem[];
    char* sAh = smem;
    char* sAl = smem + 16384;
    char* sBh = smem + 32768;
    char* sBl = smem + 49152;
    const uint32_t aAh = smem_u32(sAh), aAl = smem_u32(sAl);
    const uint32_t aBh = smem_u32(sBh), aBl = smem_u32(sBl);

    const int tid = threadIdx.x, lane = tid & 31, wid = tid >> 5;
    const int bm = blockIdx.y * 128, bn = blockIdx.x * 128;
    const int wm0 = (wid >> 2) * 64, wn0 = (wid & 3) * 32;

    float C[4][4][4] = {};

    for (int k0 = 0; k0 < Dd; k0 += 64) {
        #pragma unroll
        for (int p = 0; p < 4; ++p) {
            int u = tid + (p << 8);
            int r = u >> 3, c = u & 7;
            uint32_t so = SWZ128((uint32_t)(r * 128 + c * 16));
            size_t ga = (size_t)(bm + r) * Dd + k0 + c * 8;
            size_t gb = (size_t)(bn + r) * Dd + k0 + c * 8;
            *(uint4*)(sAh + so) = *(const uint4*)(Ah + ga);
            *(uint4*)(sAl + so) = *(const uint4*)(Al + ga);
            *(uint4*)(sBh + so) = *(const uint4*)(Bh + gb);
            *(uint4*)(sBl + so) = *(const uint4*)(Bl + gb);
        }
        __syncthreads();
        warp_mma_3<4, 4>(C, aAh, aAl, aBh, aBl, wm0, wn0, lane);
        __syncthreads();
    }

    const int m0 = bm + wm0, n0 = bn + wn0;
    #pragma unroll
    for (int m = 0; m < 4; ++m)
        #pragma unroll
        for (int n = 0; n < 4; ++n) {
            #pragma unroll
            for (int e = 0; e < 4; ++e) {
                int mm = m0 + m * 16 + (lane >> 2) + ((e >> 1) << 3);
                int nn = n0 + n * 8 + ((lane & 3) << 1) + (e & 1);
                float val = C[m][n][e] + bias[nn];
                if (MODE == 0) {
                    outf[(size_t)mm * Dd + nn] = val;
                } else {
                    const int bb = mm >> 11, ss = mm & 2047, h = nn >> 6, d = nn & 63;
                    size_t o = ((size_t)(bb * Hh + h) * HDd + d) * Ss + ss;
                    split2h(val, oh[o], ol[o]);
                }
            }
        }
}

// ---------------------------------------------------------------------------
// qk1: per (b,h) scores = q @ k^T + mask (single fp16 operands, 1 term)
// ---------------------------------------------------------------------------
__global__ __launch_bounds__(256) void qk1_mma(
    const __half* __restrict__ qm, const __half* __restrict__ km,
    const float* __restrict__ amask, const unsigned char* __restrict__ kpm,
    float* __restrict__ sc)
{
    extern __shared__ char smem[];
    char* sQ = smem;
    char* sK = smem + 16384;
    const uint32_t aQ = smem_u32(sQ), aK = smem_u32(sK);

    const int tid = threadIdx.x, lane = tid & 31, wid = tid >> 5;
    const int bn = blockIdx.x * 128, bm = blockIdx.y * 128, bh = blockIdx.z;
    const int bb = bh >> 4;

    const __half* Q = qm + (size_t)bh * Ss * HDd;
    const __half* K = km + (size_t)bh * Ss * HDd;

    #pragma unroll
    for (int p = 0; p < 4; ++p) {
        int u = tid + (p << 8);
        int r = u >> 3, c = u & 7;
        uint32_t so = SWZ128((uint32_t)(r * 128 + c * 16));
        *(uint4*)(sQ + so) = *(const uint4*)(Q + (size_t)(bm + r) * HDd + c * 8);
        *(uint4*)(sK + so) = *(const uint4*)(K + (size_t)(bn + r) * HDd + c * 8);
    }
    __syncthreads();

    float C[4][4][4] = {};
    warp_mma_1<4, 4>(C, aQ, aK, (wid >> 2) * 64, (wid & 3) * 32, lane);

    const int m0 = bm + (wid >> 2) * 64, n0 = bn + (wid & 3) * 32;
    #pragma unroll
    for (int m = 0; m < 4; ++m)
        #pragma unroll
        for (int n = 0; n < 4; ++n) {
            int qi0 = m0 + m * 16 + (lane >> 2);
            int kj  = n0 + n * 8 + ((lane & 3) << 1);
            bool p0 = kpm[bb * Ss + kj], p1 = kpm[bb * Ss + kj + 1];
            #pragma unroll
            for (int hf = 0; hf < 2; ++hf) {
                int qi = qi0 + hf * 8;
                float2 mk = *(const float2*)(amask + (size_t)qi * Ss + kj);
                float2 v;
                v.x = C[m][n][hf * 2 + 0] + mk.x;
                v.y = C[m][n][hf * 2 + 1] + mk.y;
                if (p0) v.x = -1e30f;
                if (p1) v.y = -1e30f;
                *(float2*)(sc + ((size_t)bh * Ss + qi) * Ss + kj) = v;
            }
        }
}

// ---------------------------------------------------------------------------
// Fused softmax + head average; emit probs as single fp16.
// ---------------------------------------------------------------------------
__global__ __launch_bounds__(256) void softmax_avg(const float* __restrict__ sc,
                                                   __half* __restrict__ pr,
                                                   float* __restrict__ avg)
{
    const int bi = blockIdx.x;
    const int b = bi >> 11, i = bi & 2047;
    const int t = threadIdx.x, lane = t & 31, w = t >> 5;
    __shared__ float sred[8];
    float acc[8] = {0, 0, 0, 0, 0, 0, 0, 0};

    for (int h = 0; h < Hh; ++h) {
        const size_t ro = ((size_t)(b * Hh + h) * Ss + i) * Ss;
        const float* row = sc + ro;
        float v[8];
        float mx = -3.0e38f;
        #pragma unroll
        for (int j = 0; j < 8; ++j) { v[j] = row[t + (j << 8)]; mx = fmaxf(mx, v[j]); }
        #pragma unroll
        for (int o = 16; o; o >>= 1) mx = fmaxf(mx, __shfl_xor_sync(0xffffffffu, mx, o));
        if (lane == 0) sred[w] = mx;
        __syncthreads();
        float rmax = sred[0];
        #pragma unroll
        for (int j = 1; j < 8; ++j) rmax = fmaxf(rmax, sred[j]);
        __syncthreads();
        float s = 0.0f;
        #pragma unroll
        for (int j = 0; j < 8; ++j) { v[j] = __expf(v[j] - rmax); s += v[j]; }
        #pragma unroll
        for (int o = 16; o; o >>= 1) s += __shfl_xor_sync(0xffffffffu, s, o);
        if (lane == 0) sred[w] = s;
        __syncthreads();
        float tot = 0.0f;
        #pragma unroll
        for (int j = 0; j < 8; ++j) tot += sred[j];
        __syncthreads();
        float inv = 1.0f / tot;
        #pragma unroll
        for (int j = 0; j < 8; ++j) {
            float p = v[j] * inv;
            acc[j] += p;
            pr[ro + t + (j << 8)] = __float2half_rn(p);
        }
    }
    #pragma unroll
    for (int j = 0; j < 8; ++j)
        avg[(size_t)bi * Ss + t + (j << 8)] = acc[j] * (1.0f / Hh);
}

// ---------------------------------------------------------------------------
// pv2: per (b,h) attn = P @ (vh+vl); gate; emit ao dual fp16.
// Block 128x64, BK=64, 8 warps (4m x 2n), warp tile 32x32.
// ---------------------------------------------------------------------------
__global__ __launch_bounds__(256) void pv2_mma(
    const __half* __restrict__ pm,
    const __half* __restrict__ vth, const __half* __restrict__ vtl,
    const float* __restrict__ gate,
    __half* __restrict__ aoh, __half* __restrict__ aol)
{
    extern __shared__ char smem[];
    char* sP  = smem;
    char* sVh = smem + 16384;
    char* sVl = smem + 24576;
    const uint32_t aP = smem_u32(sP), aVh = smem_u32(sVh), aVl = smem_u32(sVl);

    const int tid = threadIdx.x, lane = tid & 31, wid = tid >> 5;
    const int bm = blockIdx.x * 128, bh = blockIdx.y;
    const int bb = bh >> 4, hh = bh & 15;

    const __half* P  = pm  + (size_t)bh * Ss * Ss;
    const __half* Vh = vth + (size_t)bh * HDd * Ss;
    const __half* Vl = vtl + (size_t)bh * HDd * Ss;

    float C[2][4][4] = {};
    const int wm0 = (wid >> 1) * 32, wn0 = (wid & 1) * 32;

    for (int k0 = 0; k0 < Ss; k0 += 64) {
        #pragma unroll
        for (int p = 0; p < 4; ++p) {
            int u = tid + (p << 8);
            int r = u >> 3, c = u & 7;
            uint32_t so = SWZ128((uint32_t)(r * 128 + c * 16));
            *(uint4*)(sP + so) = *(const uint4*)(P + (size_t)(bm + r) * Ss + k0 + c * 8);
        }
        #pragma unroll
        for (int p = 0; p < 2; ++p) {
            int u = tid + (p << 8);
            int r = u >> 3, c = u & 7;
            uint32_t so = SWZ128((uint32_t)(r * 128 + c * 16));
            size_t gv = (size_t)r * Ss + k0 + c * 8;
            *(uint4*)(sVh + so) = *(const uint4*)(Vh + gv);
            *(uint4*)(sVl + so) = *(const uint4*)(Vl + gv);
        }
        __syncthreads();
        warp_mma_1A2B<2, 4>(C, aP, aVh, aVl, wm0, wn0, lane);
        __syncthreads();
    }

    #pragma unroll
    for (int m = 0; m < 2; ++m)
        #pragma unroll
        for (int n = 0; n < 4; ++n) {
            int s0 = bm + wm0 + m * 16 + (lane >> 2);
            int d  = wn0 + n * 8 + ((lane & 3) << 1);
            #pragma unroll
            for (int q = 0; q < 2; ++q) {
                int s = s0 + q * 8;
                const float* grow = gate + ((size_t)bh * Ss + s) * HDd;
                __half* doh = aoh + (size_t)(bb * Ss + s) * Dd + hh * HDd;
                __half* dol = aol + (size_t)(bb * Ss + s) * Dd + hh * HDd;
                float v0 = C[m][n][q * 2 + 0] * grow[d];
                float v1 = C[m][n][q * 2 + 1] * grow[d + 1];
                split2h(v0, doh[d], dol[d]);
                split2h(v1, doh[d + 1], dol[d + 1]);
            }
        }
}

// ---------------------------------------------------------------------------
extern "C" void kernel_launch(void* const* d_in, const int* in_sizes, int n_in,
                              void* d_out, int out_size)
{
    const float*         x     = (const float*)d_in[0];
    const float*         amask = (const float*)d_in[1];
    const unsigned char* kpm   = (const unsigned char*)d_in[2];
    const float* Wq = (const float*)d_in[3];  const float* bq = (const float*)d_in[4];
    const float* Wk = (const float*)d_in[5];  const float* bk = (const float*)d_in[6];
    const float* Wv = (const float*)d_in[7];  const float* bv = (const float*)d_in[8];
    const float* Wg = (const float*)d_in[9];  const float* bg = (const float*)d_in[10];
    const float* Wo = (const float*)d_in[11]; const float* bo = (const float*)d_in[12];

    float* out = (float*)d_out;

    __half *xh, *xl, *wq, *wk, *wg, *wvh, *wvl, *woh, *wol;
    __half *q, *k, *vth, *vtl, *pr, *aoh, *aol;
    float *gate, *sc;
    cudaGetSymbolAddress((void**)&xh,  g_xh);  cudaGetSymbolAddress((void**)&xl,  g_xl);
    cudaGetSymbolAddress((void**)&wq,  g_wq);  cudaGetSymbolAddress((void**)&wk,  g_wk);
    cudaGetSymbolAddress((void**)&wg,  g_wg);
    cudaGetSymbolAddress((void**)&wvh, g_wvh); cudaGetSymbolAddress((void**)&wvl, g_wvl);
    cudaGetSymbolAddress((void**)&woh, g_woh); cudaGetSymbolAddress((void**)&wol, g_wol);
    cudaGetSymbolAddress((void**)&q,   g_q);   cudaGetSymbolAddress((void**)&k,   g_k);
    cudaGetSymbolAddress((void**)&vth, g_vth); cudaGetSymbolAddress((void**)&vtl, g_vtl);
    cudaGetSymbolAddress((void**)&gate, g_gate);
    cudaGetSymbolAddress((void**)&sc,  g_sc);
    cudaGetSymbolAddress((void**)&pr,  g_p);
    cudaGetSymbolAddress((void**)&aoh, g_aoh); cudaGetSymbolAddress((void**)&aol, g_aol);

    const int SM_P2 = 49152;   // proj2: 3 x 16 KB
    const int SM_P3 = 65536;   // proj3: 4 x 16 KB
    const int SM_QK = 32768;   // qk1:   2 x 16 KB
    const int SM_PV = 32768;   // pv2:   16 + 8 + 8 KB
    cudaFuncSetAttribute(proj2_mma<1>, cudaFuncAttributeMaxDynamicSharedMemorySize, SM_P2);
    cudaFuncSetAttribute(proj2_mma<2>, cudaFuncAttributeMaxDynamicSharedMemorySize, SM_P2);
    cudaFuncSetAttribute(proj2_mma<3>, cudaFuncAttributeMaxDynamicSharedMemorySize, SM_P2);
    cudaFuncSetAttribute(proj3_mma<0>, cudaFuncAttributeMaxDynamicSharedMemorySize, SM_P3);
    cudaFuncSetAttribute(proj3_mma<4>, cudaFuncAttributeMaxDynamicSharedMemorySize, SM_P3);
    cudaFuncSetAttribute(qk1_mma,      cudaFuncAttributeMaxDynamicSharedMemorySize, SM_QK);
    cudaFuncSetAttribute(pv2_mma,      cudaFuncAttributeMaxDynamicSharedMemorySize, SM_PV);

    // 1. conversions
    split_f16<<<2048, 256>>>(x, xh, xl, BSZ * Dd);
    wt_1<<<dim3(32, 32), dim3(32, 8)>>>(Wq, wq);
    wt_1<<<dim3(32, 32), dim3(32, 8)>>>(Wk, wk);
    wt_1<<<dim3(32, 32), dim3(32, 8)>>>(Wg, wg);
    wt_2<<<dim3(32, 32), dim3(32, 8)>>>(Wv, wvh, wvl);
    wt_2<<<dim3(32, 32), dim3(32, 8)>>>(Wo, woh, wol);

    // 2. projections
    dim3 pg(8, 32);
    proj2_mma<2><<<pg, 256, SM_P2>>>(xh, xl, wq, bq, nullptr, q);     // q (pre-scaled)
    proj2_mma<1><<<pg, 256, SM_P2>>>(xh, xl, wk, bk, nullptr, k);     // k
    proj2_mma<3><<<pg, 256, SM_P2>>>(xh, xl, wg, bg, gate, nullptr);  // gate
    proj3_mma<4><<<pg, 256, SM_P3>>>(xh, xl, wvh, wvl, bv, nullptr, vth, vtl); // v dual

    // 3. attention
    qk1_mma<<<dim3(16, 16, 32), 256, SM_QK>>>(q, k, amask, kpm, sc);
    softmax_avg<<<BSZ, 256>>>(sc, pr, out + (size_t)BSZ * Dd);
    pv2_mma<<<dim3(16, 32), 256, SM_PV>>>(pr, vth, vtl, gate, aoh, aol);

    // 4. output projection (full precision: 3-term)
    proj3_mma<0><<<pg, 256, SM_P3>>>(aoh, aol, woh, wol, bo, out, nullptr, nullptr);
}

// round 10
// speedup vs baseline: 2.9769x; 1.0175x over previous
#include <cuda_runtime.h>
#include <cuda_fp16.h>
#include <cstdint>

#define Bb   2
#define Ss   2048
#define Dd   1024
#define Hh   16
#define HDd  64
#define BHh  32
#define BSZ  4096

// ------------------------------ scratch ------------------------------------
__device__ __half g_xh[BSZ * Dd], g_xl[BSZ * Dd];          // x dual fp16
__device__ __half g_wq[Dd * Dd], g_wk[Dd * Dd], g_wg[Dd * Dd];       // W^T single
__device__ __half g_wvh[Dd * Dd], g_wvl[Dd * Dd];                    // Wv^T dual
__device__ __half g_woh[Dd * Dd], g_wol[Dd * Dd];                    // Wo^T dual
__device__ __half g_q[BHh * Ss * HDd], g_k[BHh * Ss * HDd];          // single, head-major
__device__ __half g_vth[BHh * HDd * Ss], g_vtl[BHh * HDd * Ss];      // v^T dual [bh][d][s]
__device__ float  g_gate[BHh * Ss * HDd];
__device__ __half g_sc[(size_t)BHh * Ss * Ss];                       // scores fp16
__device__ __half g_p[(size_t)BHh * Ss * Ss];                        // probs single fp16
__device__ __half g_aoh[BSZ * Dd], g_aol[BSZ * Dd];                  // ao dual

// --------------------------- helpers ---------------------------------------
__device__ __forceinline__ uint32_t smem_u32(const void* p) {
    uint32_t a;
    asm("{ .reg .u64 t; cvta.to.shared.u64 t, %1; cvt.u32.u64 %0, t; }" : "=r"(a) : "l"(p));
    return a;
}
#define SWZ128(o) ((o) ^ (((o) >> 3) & 0x70))

__device__ __forceinline__ void ldsm4(uint32_t r[4], uint32_t addr) {
    asm volatile("ldmatrix.sync.aligned.m8n8.x4.shared.b16 {%0,%1,%2,%3}, [%4];"
                 : "=r"(r[0]), "=r"(r[1]), "=r"(r[2]), "=r"(r[3]) : "r"(addr));
}
__device__ __forceinline__ void mma16816(float c[4], const uint32_t a[4], const uint32_t b[2]) {
    asm volatile("mma.sync.aligned.m16n8k16.row.col.f32.f16.f16.f32 "
                 "{%0,%1,%2,%3}, {%4,%5,%6,%7}, {%8,%9}, {%0,%1,%2,%3};"
                 : "+f"(c[0]), "+f"(c[1]), "+f"(c[2]), "+f"(c[3])
                 : "r"(a[0]), "r"(a[1]), "r"(a[2]), "r"(a[3]), "r"(b[0]), "r"(b[1]));
}
__device__ __forceinline__ void split2h(float x, __half& h, __half& l) {
    h = __float2half_rn(x);
    l = __float2half_rn(x - __half2float(h));
}

// B-fragment loader: WN x (2 halves of k64) x4regs from a tile at (n0 rows)
#define LOAD_BFRAG(dst, abase) \
    _Pragma("unroll") \
    for (int n = 0; n < WN; ++n) \
        _Pragma("unroll") \
        for (int hf = 0; hf < 2; ++hf) { \
            uint32_t off = SWZ128((uint32_t)((n0 + n * 8 + (lane & 7)) * 128 + hf * 64 + ((lane >> 3) << 4))); \
            ldsm4((dst)[n][hf], (abase) + off); \
        }

#define AFRAG_OFF(m) \
    SWZ128((uint32_t)((m0 + (m) * 16 + (lane & 7) + (((lane >> 3) & 1) << 3)) * 128 + ks * 32 + ((lane >> 4) << 4)))

// 1 term: C += A*B
template<int WM, int WN>
__device__ __forceinline__ void warp_mma_1(
    float (&C)[WM][WN][4], uint32_t aA, uint32_t aB, int m0, int n0, int lane)
{
    uint32_t Bf[WN][2][4];
    LOAD_BFRAG(Bf, aB)
    #pragma unroll
    for (int ks = 0; ks < 4; ++ks) {
        uint32_t Af[WM][4];
        #pragma unroll
        for (int m = 0; m < WM; ++m) ldsm4(Af[m], aA + AFRAG_OFF(m));
        #pragma unroll
        for (int m = 0; m < WM; ++m)
            #pragma unroll
            for (int n = 0; n < WN; ++n)
                mma16816(C[m][n], Af[m], &Bf[n][ks >> 1][(ks & 1) << 1]);
    }
}

// 2 terms sharing B: C += A0*B + A1*B
template<int WM, int WN>
__device__ __forceinline__ void warp_mma_2A1B(
    float (&C)[WM][WN][4], uint32_t aA0, uint32_t aA1, uint32_t aB, int m0, int n0, int lane)
{
    uint32_t Bf[WN][2][4];
    LOAD_BFRAG(Bf, aB)
    #pragma unroll
    for (int ks = 0; ks < 4; ++ks) {
        uint32_t A0[WM][4], A1[WM][4];
        #pragma unroll
        for (int m = 0; m < WM; ++m) { ldsm4(A0[m], aA0 + AFRAG_OFF(m)); ldsm4(A1[m], aA1 + AFRAG_OFF(m)); }
        #pragma unroll
        for (int m = 0; m < WM; ++m)
            #pragma unroll
            for (int n = 0; n < WN; ++n) {
                const uint32_t* b = &Bf[n][ks >> 1][(ks & 1) << 1];
                mma16816(C[m][n], A0[m], b);
                mma16816(C[m][n], A1[m], b);
            }
    }
}

// 2 terms sharing A: C += A*B0 + A*B1
template<int WM, int WN>
__device__ __forceinline__ void warp_mma_1A2B(
    float (&C)[WM][WN][4], uint32_t aA, uint32_t aB0, uint32_t aB1, int m0, int n0, int lane)
{
    uint32_t B0[WN][2][4], B1[WN][2][4];
    LOAD_BFRAG(B0, aB0)
    LOAD_BFRAG(B1, aB1)
    #pragma unroll
    for (int ks = 0; ks < 4; ++ks) {
        uint32_t Af[WM][4];
        #pragma unroll
        for (int m = 0; m < WM; ++m) ldsm4(Af[m], aA + AFRAG_OFF(m));
        #pragma unroll
        for (int m = 0; m < WM; ++m)
            #pragma unroll
            for (int n = 0; n < WN; ++n) {
                mma16816(C[m][n], Af[m], &B0[n][ks >> 1][(ks & 1) << 1]);
                mma16816(C[m][n], Af[m], &B1[n][ks >> 1][(ks & 1) << 1]);
            }
    }
}

// 3 terms: C += Ah*Bh + Ah*Bl + Al*Bh
template<int WM, int WN>
__device__ __forceinline__ void warp_mma_3(
    float (&C)[WM][WN][4], uint32_t aAh, uint32_t aAl, uint32_t aBh, uint32_t aBl,
    int m0, int n0, int lane)
{
    uint32_t Bh[WN][2][4], Bl[WN][2][4];
    LOAD_BFRAG(Bh, aBh)
    LOAD_BFRAG(Bl, aBl)
    #pragma unroll
    for (int ks = 0; ks < 4; ++ks) {
        uint32_t Ah[WM][4], Al[WM][4];
        #pragma unroll
        for (int m = 0; m < WM; ++m) { ldsm4(Ah[m], aAh + AFRAG_OFF(m)); ldsm4(Al[m], aAl + AFRAG_OFF(m)); }
        #pragma unroll
        for (int m = 0; m < WM; ++m)
            #pragma unroll
            for (int n = 0; n < WN; ++n) {
                const uint32_t* bh = &Bh[n][ks >> 1][(ks & 1) << 1];
                const uint32_t* bl = &Bl[n][ks >> 1][(ks & 1) << 1];
                mma16816(C[m][n], Ah[m], bh);
                mma16816(C[m][n], Ah[m], bl);
                mma16816(C[m][n], Al[m], bh);
            }
    }
}

// -------------------- conversion kernels -----------------------------------
__global__ __launch_bounds__(256) void split_f16(const float* __restrict__ in,
                                                 __half* __restrict__ hi,
                                                 __half* __restrict__ lo, int n) {
    for (int i = blockIdx.x * 256 + threadIdx.x; i < n; i += gridDim.x * 256)
        split2h(in[i], hi[i], lo[i]);
}

// W [K,N] row-major -> Wt[n][k], single fp16
__global__ __launch_bounds__(256) void wt_1(const float* __restrict__ W, __half* __restrict__ t1) {
    __shared__ float t[32][33];
    const int tx = threadIdx.x, ty = threadIdx.y;
    const int n0 = blockIdx.x * 32, k0 = blockIdx.y * 32;
    #pragma unroll
    for (int i = 0; i < 4; ++i)
        t[ty + 8 * i][tx] = W[(size_t)(k0 + ty + 8 * i) * Dd + n0 + tx];
    __syncthreads();
    #pragma unroll
    for (int i = 0; i < 4; ++i)
        t1[(size_t)(n0 + ty + 8 * i) * Dd + k0 + tx] = __float2half_rn(t[tx][ty + 8 * i]);
}

// W -> Wt dual fp16
__global__ __launch_bounds__(256) void wt_2(const float* __restrict__ W,
                                            __half* __restrict__ th, __half* __restrict__ tl) {
    __shared__ float t[32][33];
    const int tx = threadIdx.x, ty = threadIdx.y;
    const int n0 = blockIdx.x * 32, k0 = blockIdx.y * 32;
    #pragma unroll
    for (int i = 0; i < 4; ++i)
        t[ty + 8 * i][tx] = W[(size_t)(k0 + ty + 8 * i) * Dd + n0 + tx];
    __syncthreads();
    #pragma unroll
    for (int i = 0; i < 4; ++i) {
        size_t o = (size_t)(n0 + ty + 8 * i) * Dd + k0 + tx;
        split2h(t[tx][ty + 8 * i], th[o], tl[o]);
    }
}

// ---------------------------------------------------------------------------
// proj2: C(4096,1024) = (xh+xl) @ W^T + bias, 2 terms.
// MODE: 1 k single head-major; 2 q single head-major *0.125; 3 gate sigmoid fp32
// ---------------------------------------------------------------------------
template<int MODE>
__global__ __launch_bounds__(256) void proj2_mma(
    const __half* __restrict__ Ah, const __half* __restrict__ Al,
    const __half* __restrict__ Bw, const float* __restrict__ bias,
    float* __restrict__ outf, __half* __restrict__ oh)
{
    extern __shared__ char smem[];
    char* sAh = smem;
    char* sAl = smem + 16384;
    char* sBw = smem + 32768;
    const uint32_t aAh = smem_u32(sAh), aAl = smem_u32(sAl), aBw = smem_u32(sBw);

    const int tid = threadIdx.x, lane = tid & 31, wid = tid >> 5;
    const int bm = blockIdx.y * 128, bn = blockIdx.x * 128;
    const int wm0 = (wid >> 2) * 64, wn0 = (wid & 3) * 32;

    float C[4][4][4] = {};

    for (int k0 = 0; k0 < Dd; k0 += 64) {
        #pragma unroll
        for (int p = 0; p < 4; ++p) {
            int u = tid + (p << 8);
            int r = u >> 3, c = u & 7;
            uint32_t so = SWZ128((uint32_t)(r * 128 + c * 16));
            size_t ga = (size_t)(bm + r) * Dd + k0 + c * 8;
            size_t gb = (size_t)(bn + r) * Dd + k0 + c * 8;
            *(uint4*)(sAh + so) = *(const uint4*)(Ah + ga);
            *(uint4*)(sAl + so) = *(const uint4*)(Al + ga);
            *(uint4*)(sBw + so) = *(const uint4*)(Bw + gb);
        }
        __syncthreads();
        warp_mma_2A1B<4, 4>(C, aAh, aAl, aBw, wm0, wn0, lane);
        __syncthreads();
    }

    const int m0 = bm + wm0, n0 = bn + wn0;
    #pragma unroll
    for (int m = 0; m < 4; ++m)
        #pragma unroll
        for (int n = 0; n < 4; ++n) {
            #pragma unroll
            for (int e = 0; e < 4; ++e) {
                int mm = m0 + m * 16 + (lane >> 2) + ((e >> 1) << 3);
                int nn = n0 + n * 8 + ((lane & 3) << 1) + (e & 1);
                float val = C[m][n][e] + bias[nn];
                const int bb = mm >> 11, ss = mm & 2047, h = nn >> 6, d = nn & 63;
                size_t o = ((size_t)(bb * Hh + h) * Ss + ss) * HDd + d;
                if (MODE == 2) oh[o] = __float2half_rn(val * 0.125f);
                else if (MODE == 1) oh[o] = __float2half_rn(val);
                else outf[o] = 1.0f / (1.0f + __expf(-val));
            }
        }
}

// ---------------------------------------------------------------------------
// proj3: C = (Ah+Al) @ (Bh+Bl)^T + bias, 3 terms.
// MODE: 0 fp32 row-major out; 4 v dual transposed [bh][d][s]
// ---------------------------------------------------------------------------
template<int MODE>
__global__ __launch_bounds__(256) void proj3_mma(
    const __half* __restrict__ Ah, const __half* __restrict__ Al,
    const __half* __restrict__ Bh, const __half* __restrict__ Bl,
    const float* __restrict__ bias,
    float* __restrict__ outf, __half* __restrict__ oh, __half* __restrict__ ol)
{
    extern __shared__ char smem[];
    char* sAh = smem;
    char* sAl = smem + 16384;
    char* sBh = smem + 32768;
    char* sBl = smem + 49152;
    const uint32_t aAh = smem_u32(sAh), aAl = smem_u32(sAl);
    const uint32_t aBh = smem_u32(sBh), aBl = smem_u32(sBl);

    const int tid = threadIdx.x, lane = tid & 31, wid = tid >> 5;
    const int bm = blockIdx.y * 128, bn = blockIdx.x * 128;
    const int wm0 = (wid >> 2) * 64, wn0 = (wid & 3) * 32;

    float C[4][4][4] = {};

    for (int k0 = 0; k0 < Dd; k0 += 64) {
        #pragma unroll
        for (int p = 0; p < 4; ++p) {
            int u = tid + (p << 8);
            int r = u >> 3, c = u & 7;
            uint32_t so = SWZ128((uint32_t)(r * 128 + c * 16));
            size_t ga = (size_t)(bm + r) * Dd + k0 + c * 8;
            size_t gb = (size_t)(bn + r) * Dd + k0 + c * 8;
            *(uint4*)(sAh + so) = *(const uint4*)(Ah + ga);
            *(uint4*)(sAl + so) = *(const uint4*)(Al + ga);
            *(uint4*)(sBh + so) = *(const uint4*)(Bh + gb);
            *(uint4*)(sBl + so) = *(const uint4*)(Bl + gb);
        }
        __syncthreads();
        warp_mma_3<4, 4>(C, aAh, aAl, aBh, aBl, wm0, wn0, lane);
        __syncthreads();
    }

    const int m0 = bm + wm0, n0 = bn + wn0;
    #pragma unroll
    for (int m = 0; m < 4; ++m)
        #pragma unroll
        for (int n = 0; n < 4; ++n) {
            #pragma unroll
            for (int e = 0; e < 4; ++e) {
                int mm = m0 + m * 16 + (lane >> 2) + ((e >> 1) << 3);
                int nn = n0 + n * 8 + ((lane & 3) << 1) + (e & 1);
                float val = C[m][n][e] + bias[nn];
                if (MODE == 0) {
                    outf[(size_t)mm * Dd + nn] = val;
                } else {
                    const int bb = mm >> 11, ss = mm & 2047, h = nn >> 6, d = nn & 63;
                    size_t o = ((size_t)(bb * Hh + h) * HDd + d) * Ss + ss;
                    split2h(val, oh[o], ol[o]);
                }
            }
        }
}

// ---------------------------------------------------------------------------
// qk1: per (b,h) scores = q @ k^T + mask -> fp16 scores (single term)
// ---------------------------------------------------------------------------
__global__ __launch_bounds__(256) void qk1_mma(
    const __half* __restrict__ qm, const __half* __restrict__ km,
    const float* __restrict__ amask, const unsigned char* __restrict__ kpm,
    __half* __restrict__ sc)
{
    extern __shared__ char smem[];
    char* sQ = smem;
    char* sK = smem + 16384;
    const uint32_t aQ = smem_u32(sQ), aK = smem_u32(sK);

    const int tid = threadIdx.x, lane = tid & 31, wid = tid >> 5;
    const int bn = blockIdx.x * 128, bm = blockIdx.y * 128, bh = blockIdx.z;
    const int bb = bh >> 4;

    const __half* Q = qm + (size_t)bh * Ss * HDd;
    const __half* K = km + (size_t)bh * Ss * HDd;

    #pragma unroll
    for (int p = 0; p < 4; ++p) {
        int u = tid + (p << 8);
        int r = u >> 3, c = u & 7;
        uint32_t so = SWZ128((uint32_t)(r * 128 + c * 16));
        *(uint4*)(sQ + so) = *(const uint4*)(Q + (size_t)(bm + r) * HDd + c * 8);
        *(uint4*)(sK + so) = *(const uint4*)(K + (size_t)(bn + r) * HDd + c * 8);
    }
    __syncthreads();

    float C[4][4][4] = {};
    warp_mma_1<4, 4>(C, aQ, aK, (wid >> 2) * 64, (wid & 3) * 32, lane);

    const int m0 = bm + (wid >> 2) * 64, n0 = bn + (wid & 3) * 32;
    #pragma unroll
    for (int m = 0; m < 4; ++m)
        #pragma unroll
        for (int n = 0; n < 4; ++n) {
            int qi0 = m0 + m * 16 + (lane >> 2);
            int kj  = n0 + n * 8 + ((lane & 3) << 1);
            bool p0 = kpm[bb * Ss + kj], p1 = kpm[bb * Ss + kj + 1];
            #pragma unroll
            for (int hf = 0; hf < 2; ++hf) {
                int qi = qi0 + hf * 8;
                float2 mk = *(const float2*)(amask + (size_t)qi * Ss + kj);
                float vx = C[m][n][hf * 2 + 0] + mk.x;
                float vy = C[m][n][hf * 2 + 1] + mk.y;
                if (p0) vx = -30000.0f;   // fp16-safe "-inf": exp -> 0
                if (p1) vy = -30000.0f;
                __half2 hv = __floats2half2_rn(vx, vy);
                *(__half2*)(sc + ((size_t)bh * Ss + qi) * Ss + kj) = hv;
            }
        }
}

// ---------------------------------------------------------------------------
// Fused softmax + head average; reads fp16 scores, emits fp16 probs.
// ---------------------------------------------------------------------------
__global__ __launch_bounds__(256) void softmax_avg(const __half* __restrict__ sc,
                                                   __half* __restrict__ pr,
                                                   float* __restrict__ avg)
{
    const int bi = blockIdx.x;
    const int b = bi >> 11, i = bi & 2047;
    const int t = threadIdx.x, lane = t & 31, w = t >> 5;
    __shared__ float sred[8];
    float acc[8] = {0, 0, 0, 0, 0, 0, 0, 0};

    for (int h = 0; h < Hh; ++h) {
        const size_t ro = ((size_t)(b * Hh + h) * Ss + i) * Ss;
        const __half* row = sc + ro;
        float v[8];
        float mx = -3.0e38f;
        #pragma unroll
        for (int j = 0; j < 8; ++j) { v[j] = __half2float(row[t + (j << 8)]); mx = fmaxf(mx, v[j]); }
        #pragma unroll
        for (int o = 16; o; o >>= 1) mx = fmaxf(mx, __shfl_xor_sync(0xffffffffu, mx, o));
        if (lane == 0) sred[w] = mx;
        __syncthreads();
        float rmax = sred[0];
        #pragma unroll
        for (int j = 1; j < 8; ++j) rmax = fmaxf(rmax, sred[j]);
        __syncthreads();
        float s = 0.0f;
        #pragma unroll
        for (int j = 0; j < 8; ++j) { v[j] = __expf(v[j] - rmax); s += v[j]; }
        #pragma unroll
        for (int o = 16; o; o >>= 1) s += __shfl_xor_sync(0xffffffffu, s, o);
        if (lane == 0) sred[w] = s;
        __syncthreads();
        float tot = 0.0f;
        #pragma unroll
        for (int j = 0; j < 8; ++j) tot += sred[j];
        __syncthreads();
        float inv = 1.0f / tot;
        #pragma unroll
        for (int j = 0; j < 8; ++j) {
            float p = v[j] * inv;
            acc[j] += p;
            pr[ro + t + (j << 8)] = __float2half_rn(p);
        }
    }
    #pragma unroll
    for (int j = 0; j < 8; ++j)
        avg[(size_t)bi * Ss + t + (j << 8)] = acc[j] * (1.0f / Hh);
}

// ---------------------------------------------------------------------------
// pv2: per (b,h) attn = P @ (vh+vl); gate; emit ao dual fp16.
// Block 128x64, BK=64, 8 warps (4m x 2n), warp tile 32x32.
// ---------------------------------------------------------------------------
__global__ __launch_bounds__(256) void pv2_mma(
    const __half* __restrict__ pm,
    const __half* __restrict__ vth, const __half* __restrict__ vtl,
    const float* __restrict__ gate,
    __half* __restrict__ aoh, __half* __restrict__ aol)
{
    extern __shared__ char smem[];
    char* sP  = smem;
    char* sVh = smem + 16384;
    char* sVl = smem + 24576;
    const uint32_t aP = smem_u32(sP), aVh = smem_u32(sVh), aVl = smem_u32(sVl);

    const int tid = threadIdx.x, lane = tid & 31, wid = tid >> 5;
    const int bm = blockIdx.x * 128, bh = blockIdx.y;
    const int bb = bh >> 4, hh = bh & 15;

    const __half* P  = pm  + (size_t)bh * Ss * Ss;
    const __half* Vh = vth + (size_t)bh * HDd * Ss;
    const __half* Vl = vtl + (size_t)bh * HDd * Ss;

    float C[2][4][4] = {};
    const int wm0 = (wid >> 1) * 32, wn0 = (wid & 1) * 32;

    for (int k0 = 0; k0 < Ss; k0 += 64) {
        #pragma unroll
        for (int p = 0; p < 4; ++p) {
            int u = tid + (p << 8);
            int r = u >> 3, c = u & 7;
            uint32_t so = SWZ128((uint32_t)(r * 128 + c * 16));
            *(uint4*)(sP + so) = *(const uint4*)(P + (size_t)(bm + r) * Ss + k0 + c * 8);
        }
        #pragma unroll
        for (int p = 0; p < 2; ++p) {
            int u = tid + (p << 8);
            int r = u >> 3, c = u & 7;
            uint32_t so = SWZ128((uint32_t)(r * 128 + c * 16));
            size_t gv = (size_t)r * Ss + k0 + c * 8;
            *(uint4*)(sVh + so) = *(const uint4*)(Vh + gv);
            *(uint4*)(sVl + so) = *(const uint4*)(Vl + gv);
        }
        __syncthreads();
        warp_mma_1A2B<2, 4>(C, aP, aVh, aVl, wm0, wn0, lane);
        __syncthreads();
    }

    #pragma unroll
    for (int m = 0; m < 2; ++m)
        #pragma unroll
        for (int n = 0; n < 4; ++n) {
            int s0 = bm + wm0 + m * 16 + (lane >> 2);
            int d  = wn0 + n * 8 + ((lane & 3) << 1);
            #pragma unroll
            for (int q = 0; q < 2; ++q) {
                int s = s0 + q * 8;
                const float* grow = gate + ((size_t)bh * Ss + s) * HDd;
                __half* doh = aoh + (size_t)(bb * Ss + s) * Dd + hh * HDd;
                __half* dol = aol + (size_t)(bb * Ss + s) * Dd + hh * HDd;
                float v0 = C[m][n][q * 2 + 0] * grow[d];
                float v1 = C[m][n][q * 2 + 1] * grow[d + 1];
                split2h(v0, doh[d], dol[d]);
                split2h(v1, doh[d + 1], dol[d + 1]);
            }
        }
}

// ---------------------------------------------------------------------------
extern "C" void kernel_launch(void* const* d_in, const int* in_sizes, int n_in,
                              void* d_out, int out_size)
{
    const float*         x     = (const float*)d_in[0];
    const float*         amask = (const float*)d_in[1];
    const unsigned char* kpm   = (const unsigned char*)d_in[2];
    const float* Wq = (const float*)d_in[3];  const float* bq = (const float*)d_in[4];
    const float* Wk = (const float*)d_in[5];  const float* bk = (const float*)d_in[6];
    const float* Wv = (const float*)d_in[7];  const float* bv = (const float*)d_in[8];
    const float* Wg = (const float*)d_in[9];  const float* bg = (const float*)d_in[10];
    const float* Wo = (const float*)d_in[11]; const float* bo = (const float*)d_in[12];

    float* out = (float*)d_out;

    __half *xh, *xl, *wq, *wk, *wg, *wvh, *wvl, *woh, *wol;
    __half *q, *k, *vth, *vtl, *pr, *aoh, *aol, *sc;
    float *gate;
    cudaGetSymbolAddress((void**)&xh,  g_xh);  cudaGetSymbolAddress((void**)&xl,  g_xl);
    cudaGetSymbolAddress((void**)&wq,  g_wq);  cudaGetSymbolAddress((void**)&wk,  g_wk);
    cudaGetSymbolAddress((void**)&wg,  g_wg);
    cudaGetSymbolAddress((void**)&wvh, g_wvh); cudaGetSymbolAddress((void**)&wvl, g_wvl);
    cudaGetSymbolAddress((void**)&woh, g_woh); cudaGetSymbolAddress((void**)&wol, g_wol);
    cudaGetSymbolAddress((void**)&q,   g_q);   cudaGetSymbolAddress((void**)&k,   g_k);
    cudaGetSymbolAddress((void**)&vth, g_vth); cudaGetSymbolAddress((void**)&vtl, g_vtl);
    cudaGetSymbolAddress((void**)&gate, g_gate);
    cudaGetSymbolAddress((void**)&sc,  g_sc);
    cudaGetSymbolAddress((void**)&pr,  g_p);
    cudaGetSymbolAddress((void**)&aoh, g_aoh); cudaGetSymbolAddress((void**)&aol, g_aol);

    const int SM_P2 = 49152;   // proj2: 3 x 16 KB
    const int SM_P3 = 65536;   // proj3: 4 x 16 KB
    const int SM_QK = 32768;   // qk1:   2 x 16 KB
    const int SM_PV = 32768;   // pv2:   16 + 8 + 8 KB
    cudaFuncSetAttribute(proj2_mma<1>, cudaFuncAttributeMaxDynamicSharedMemorySize, SM_P2);
    cudaFuncSetAttribute(proj2_mma<2>, cudaFuncAttributeMaxDynamicSharedMemorySize, SM_P2);
    cudaFuncSetAttribute(proj2_mma<3>, cudaFuncAttributeMaxDynamicSharedMemorySize, SM_P2);
    cudaFuncSetAttribute(proj3_mma<0>, cudaFuncAttributeMaxDynamicSharedMemorySize, SM_P3);
    cudaFuncSetAttribute(proj3_mma<4>, cudaFuncAttributeMaxDynamicSharedMemorySize, SM_P3);
    cudaFuncSetAttribute(qk1_mma,      cudaFuncAttributeMaxDynamicSharedMemorySize, SM_QK);
    cudaFuncSetAttribute(pv2_mma,      cudaFuncAttributeMaxDynamicSharedMemorySize, SM_PV);

    // 1. conversions
    split_f16<<<2048, 256>>>(x, xh, xl, BSZ * Dd);
    wt_1<<<dim3(32, 32), dim3(32, 8)>>>(Wq, wq);
    wt_1<<<dim3(32, 32), dim3(32, 8)>>>(Wk, wk);
    wt_1<<<dim3(32, 32), dim3(32, 8)>>>(Wg, wg);
    wt_2<<<dim3(32, 32), dim3(32, 8)>>>(Wv, wvh, wvl);
    wt_2<<<dim3(32, 32), dim3(32, 8)>>>(Wo, woh, wol);

    // 2. projections
    dim3 pg(8, 32);
    proj2_mma<2><<<pg, 256, SM_P2>>>(xh, xl, wq, bq, nullptr, q);     // q (pre-scaled)
    proj2_mma<1><<<pg, 256, SM_P2>>>(xh, xl, wk, bk, nullptr, k);     // k
    proj2_mma<3><<<pg, 256, SM_P2>>>(xh, xl, wg, bg, gate, nullptr);  // gate
    proj3_mma<4><<<pg, 256, SM_P3>>>(xh, xl, wvh, wvl, bv, nullptr, vth, vtl); // v dual

    // 3. attention
    qk1_mma<<<dim3(16, 16, 32), 256, SM_QK>>>(q, k, amask, kpm, sc);
    softmax_avg<<<BSZ, 256>>>(sc, pr, out + (size_t)BSZ * Dd);
    pv2_mma<<<dim3(16, 32), 256, SM_PV>>>(pr, vth, vtl, gate, aoh, aol);

    // 4. output projection (full precision: 3-term)
    proj3_mma<0><<<pg, 256, SM_P3>>>(aoh, aol, woh, wol, bo, out, nullptr, nullptr);
}

// round 12
// speedup vs baseline: 3.0849x; 1.0363x over previous
#include <cuda_runtime.h>
#include <cuda_fp16.h>
#include <cstdint>

#define Bb   2
#define Ss   2048
#define Dd   1024
#define Hh   16
#define HDd  64
#define BHh  32
#define BSZ  4096

// ------------------------------ scratch ------------------------------------
__device__ __half g_xh[BSZ * Dd], g_xl[BSZ * Dd];          // x dual fp16
__device__ __half g_wq[Dd * Dd], g_wk[Dd * Dd], g_wg[Dd * Dd];       // W^T single
__device__ __half g_wvh[Dd * Dd], g_wvl[Dd * Dd];                    // Wv^T dual
__device__ __half g_woh[Dd * Dd], g_wol[Dd * Dd];                    // Wo^T dual
__device__ __half g_q[BHh * Ss * HDd], g_k[BHh * Ss * HDd];          // single, head-major
__device__ __half g_vth[BHh * HDd * Ss], g_vtl[BHh * HDd * Ss];      // v^T dual [bh][d][s]
__device__ float  g_gate[BHh * Ss * HDd];
__device__ __half g_sc[(size_t)BHh * Ss * Ss];                       // scores fp16
__device__ __half g_p[(size_t)BHh * Ss * Ss];                        // probs single fp16
__device__ __half g_aoh[BSZ * Dd], g_aol[BSZ * Dd];                  // ao dual

// --------------------------- helpers ---------------------------------------
__device__ __forceinline__ uint32_t smem_u32(const void* p) {
    uint32_t a;
    asm("{ .reg .u64 t; cvta.to.shared.u64 t, %1; cvt.u32.u64 %0, t; }" : "=r"(a) : "l"(p));
    return a;
}
#define SWZ128(o) ((o) ^ (((o) >> 3) & 0x70))

__device__ __forceinline__ void ldsm4(uint32_t r[4], uint32_t addr) {
    asm volatile("ldmatrix.sync.aligned.m8n8.x4.shared.b16 {%0,%1,%2,%3}, [%4];"
                 : "=r"(r[0]), "=r"(r[1]), "=r"(r[2]), "=r"(r[3]) : "r"(addr));
}
__device__ __forceinline__ void mma16816(float c[4], const uint32_t a[4], const uint32_t b[2]) {
    asm volatile("mma.sync.aligned.m16n8k16.row.col.f32.f16.f16.f32 "
                 "{%0,%1,%2,%3}, {%4,%5,%6,%7}, {%8,%9}, {%0,%1,%2,%3};"
                 : "+f"(c[0]), "+f"(c[1]), "+f"(c[2]), "+f"(c[3])
                 : "r"(a[0]), "r"(a[1]), "r"(a[2]), "r"(a[3]), "r"(b[0]), "r"(b[1]));
}
__device__ __forceinline__ void split2h(float x, __half& h, __half& l) {
    h = __float2half_rn(x);
    l = __float2half_rn(x - __half2float(h));
}

// B-fragment loader: WN x (2 halves of k64) x4regs from a tile at (n0 rows)
#define LOAD_BFRAG(dst, abase) \
    _Pragma("unroll") \
    for (int n = 0; n < WN; ++n) \
        _Pragma("unroll") \
        for (int hf = 0; hf < 2; ++hf) { \
            uint32_t off = SWZ128((uint32_t)((n0 + n * 8 + (lane & 7)) * 128 + hf * 64 + ((lane >> 3) << 4))); \
            ldsm4((dst)[n][hf], (abase) + off); \
        }

#define AFRAG_OFF(m) \
    SWZ128((uint32_t)((m0 + (m) * 16 + (lane & 7) + (((lane >> 3) & 1) << 3)) * 128 + ks * 32 + ((lane >> 4) << 4)))

// 1 term: C += A*B
template<int WM, int WN>
__device__ __forceinline__ void warp_mma_1(
    float (&C)[WM][WN][4], uint32_t aA, uint32_t aB, int m0, int n0, int lane)
{
    uint32_t Bf[WN][2][4];
    LOAD_BFRAG(Bf, aB)
    #pragma unroll
    for (int ks = 0; ks < 4; ++ks) {
        uint32_t Af[WM][4];
        #pragma unroll
        for (int m = 0; m < WM; ++m) ldsm4(Af[m], aA + AFRAG_OFF(m));
        #pragma unroll
        for (int m = 0; m < WM; ++m)
            #pragma unroll
            for (int n = 0; n < WN; ++n)
                mma16816(C[m][n], Af[m], &Bf[n][ks >> 1][(ks & 1) << 1]);
    }
}

// 2 terms sharing B: C += A0*B + A1*B
template<int WM, int WN>
__device__ __forceinline__ void warp_mma_2A1B(
    float (&C)[WM][WN][4], uint32_t aA0, uint32_t aA1, uint32_t aB, int m0, int n0, int lane)
{
    uint32_t Bf[WN][2][4];
    LOAD_BFRAG(Bf, aB)
    #pragma unroll
    for (int ks = 0; ks < 4; ++ks) {
        uint32_t A0[WM][4], A1[WM][4];
        #pragma unroll
        for (int m = 0; m < WM; ++m) { ldsm4(A0[m], aA0 + AFRAG_OFF(m)); ldsm4(A1[m], aA1 + AFRAG_OFF(m)); }
        #pragma unroll
        for (int m = 0; m < WM; ++m)
            #pragma unroll
            for (int n = 0; n < WN; ++n) {
                const uint32_t* b = &Bf[n][ks >> 1][(ks & 1) << 1];
                mma16816(C[m][n], A0[m], b);
                mma16816(C[m][n], A1[m], b);
            }
    }
}

// 2 terms sharing A: C += A*B0 + A*B1
template<int WM, int WN>
__device__ __forceinline__ void warp_mma_1A2B(
    float (&C)[WM][WN][4], uint32_t aA, uint32_t aB0, uint32_t aB1, int m0, int n0, int lane)
{
    uint32_t B0[WN][2][4], B1[WN][2][4];
    LOAD_BFRAG(B0, aB0)
    LOAD_BFRAG(B1, aB1)
    #pragma unroll
    for (int ks = 0; ks < 4; ++ks) {
        uint32_t Af[WM][4];
        #pragma unroll
        for (int m = 0; m < WM; ++m) ldsm4(Af[m], aA + AFRAG_OFF(m));
        #pragma unroll
        for (int m = 0; m < WM; ++m)
            #pragma unroll
            for (int n = 0; n < WN; ++n) {
                mma16816(C[m][n], Af[m], &B0[n][ks >> 1][(ks & 1) << 1]);
                mma16816(C[m][n], Af[m], &B1[n][ks >> 1][(ks & 1) << 1]);
            }
    }
}

// 3 terms: C += Ah*Bh + Ah*Bl + Al*Bh
template<int WM, int WN>
__device__ __forceinline__ void warp_mma_3(
    float (&C)[WM][WN][4], uint32_t aAh, uint32_t aAl, uint32_t aBh, uint32_t aBl,
    int m0, int n0, int lane)
{
    uint32_t Bh[WN][2][4], Bl[WN][2][4];
    LOAD_BFRAG(Bh, aBh)
    LOAD_BFRAG(Bl, aBl)
    #pragma unroll
    for (int ks = 0; ks < 4; ++ks) {
        uint32_t Ah[WM][4], Al[WM][4];
        #pragma unroll
        for (int m = 0; m < WM; ++m) { ldsm4(Ah[m], aAh + AFRAG_OFF(m)); ldsm4(Al[m], aAl + AFRAG_OFF(m)); }
        #pragma unroll
        for (int m = 0; m < WM; ++m)
            #pragma unroll
            for (int n = 0; n < WN; ++n) {
                const uint32_t* bh = &Bh[n][ks >> 1][(ks & 1) << 1];
                const uint32_t* bl = &Bl[n][ks >> 1][(ks & 1) << 1];
                mma16816(C[m][n], Ah[m], bh);
                mma16816(C[m][n], Ah[m], bl);
                mma16816(C[m][n], Al[m], bh);
            }
    }
}

// -------------------- conversion kernels -----------------------------------
__global__ __launch_bounds__(256) void split_f16(const float* __restrict__ in,
                                                 __half* __restrict__ hi,
                                                 __half* __restrict__ lo, int n) {
    for (int i = blockIdx.x * 256 + threadIdx.x; i < n; i += gridDim.x * 256)
        split2h(in[i], hi[i], lo[i]);
}

// W [K,N] row-major -> Wt[n][k], single fp16
__global__ __launch_bounds__(256) void wt_1(const float* __restrict__ W, __half* __restrict__ t1) {
    __shared__ float t[32][33];
    const int tx = threadIdx.x, ty = threadIdx.y;
    const int n0 = blockIdx.x * 32, k0 = blockIdx.y * 32;
    #pragma unroll
    for (int i = 0; i < 4; ++i)
        t[ty + 8 * i][tx] = W[(size_t)(k0 + ty + 8 * i) * Dd + n0 + tx];
    __syncthreads();
    #pragma unroll
    for (int i = 0; i < 4; ++i)
        t1[(size_t)(n0 + ty + 8 * i) * Dd + k0 + tx] = __float2half_rn(t[tx][ty + 8 * i]);
}

// W -> Wt dual fp16
__global__ __launch_bounds__(256) void wt_2(const float* __restrict__ W,
                                            __half* __restrict__ th, __half* __restrict__ tl) {
    __shared__ float t[32][33];
    const int tx = threadIdx.x, ty = threadIdx.y;
    const int n0 = blockIdx.x * 32, k0 = blockIdx.y * 32;
    #pragma unroll
    for (int i = 0; i < 4; ++i)
        t[ty + 8 * i][tx] = W[(size_t)(k0 + ty + 8 * i) * Dd + n0 + tx];
    __syncthreads();
    #pragma unroll
    for (int i = 0; i < 4; ++i) {
        size_t o = (size_t)(n0 + ty + 8 * i) * Dd + k0 + tx;
        split2h(t[tx][ty + 8 * i], th[o], tl[o]);
    }
}

// ---------------------------------------------------------------------------
// proj2: C(4096,1024) = (xh+xl) @ W^T + bias, 2 terms.
// MODE: 1 k single head-major; 2 q single head-major *0.125; 3 gate sigmoid fp32
// ---------------------------------------------------------------------------
template<int MODE>
__global__ __launch_bounds__(256) void proj2_mma(
    const __half* __restrict__ Ah, const __half* __restrict__ Al,
    const __half* __restrict__ Bw, const float* __restrict__ bias,
    float* __restrict__ outf, __half* __restrict__ oh)
{
    extern __shared__ char smem[];
    char* sAh = smem;
    char* sAl = smem + 16384;
    char* sBw = smem + 32768;
    const uint32_t aAh = smem_u32(sAh), aAl = smem_u32(sAl), aBw = smem_u32(sBw);

    const int tid = threadIdx.x, lane = tid & 31, wid = tid >> 5;
    const int bm = blockIdx.y * 128, bn = blockIdx.x * 128;
    const int wm0 = (wid >> 2) * 64, wn0 = (wid & 3) * 32;

    float C[4][4][4] = {};

    for (int k0 = 0; k0 < Dd; k0 += 64) {
        #pragma unroll
        for (int p = 0; p < 4; ++p) {
            int u = tid + (p << 8);
            int r = u >> 3, c = u & 7;
            uint32_t so = SWZ128((uint32_t)(r * 128 + c * 16));
            size_t ga = (size_t)(bm + r) * Dd + k0 + c * 8;
            size_t gb = (size_t)(bn + r) * Dd + k0 + c * 8;
            *(uint4*)(sAh + so) = *(const uint4*)(Ah + ga);
            *(uint4*)(sAl + so) = *(const uint4*)(Al + ga);
            *(uint4*)(sBw + so) = *(const uint4*)(Bw + gb);
        }
        __syncthreads();
        warp_mma_2A1B<4, 4>(C, aAh, aAl, aBw, wm0, wn0, lane);
        __syncthreads();
    }

    const int m0 = bm + wm0, n0 = bn + wn0;
    #pragma unroll
    for (int m = 0; m < 4; ++m)
        #pragma unroll
        for (int n = 0; n < 4; ++n) {
            #pragma unroll
            for (int e = 0; e < 4; ++e) {
                int mm = m0 + m * 16 + (lane >> 2) + ((e >> 1) << 3);
                int nn = n0 + n * 8 + ((lane & 3) << 1) + (e & 1);
                float val = C[m][n][e] + bias[nn];
                const int bb = mm >> 11, ss = mm & 2047, h = nn >> 6, d = nn & 63;
                size_t o = ((size_t)(bb * Hh + h) * Ss + ss) * HDd + d;
                if (MODE == 2) oh[o] = __float2half_rn(val * 0.125f);
                else if (MODE == 1) oh[o] = __float2half_rn(val);
                else outf[o] = 1.0f / (1.0f + __expf(-val));
            }
        }
}

// ---------------------------------------------------------------------------
// proj3: C = (Ah+Al) @ (Bh+Bl)^T + bias, 3 terms.
// MODE: 0 fp32 row-major out; 4 v dual transposed [bh][d][s]
// ---------------------------------------------------------------------------
template<int MODE>
__global__ __launch_bounds__(256) void proj3_mma(
    const __half* __restrict__ Ah, const __half* __restrict__ Al,
    const __half* __restrict__ Bh, const __half* __restrict__ Bl,
    const float* __restrict__ bias,
    float* __restrict__ outf, __half* __restrict__ oh, __half* __restrict__ ol)
{
    extern __shared__ char smem[];
    char* sAh = smem;
    char* sAl = smem + 16384;
    char* sBh = smem + 32768;
    char* sBl = smem + 49152;
    const uint32_t aAh = smem_u32(sAh), aAl = smem_u32(sAl);
    const uint32_t aBh = smem_u32(sBh), aBl = smem_u32(sBl);

    const int tid = threadIdx.x, lane = tid & 31, wid = tid >> 5;
    const int bm = blockIdx.y * 128, bn = blockIdx.x * 128;
    const int wm0 = (wid >> 2) * 64, wn0 = (wid & 3) * 32;

    float C[4][4][4] = {};

    for (int k0 = 0; k0 < Dd; k0 += 64) {
        #pragma unroll
        for (int p = 0; p < 4; ++p) {
            int u = tid + (p << 8);
            int r = u >> 3, c = u & 7;
            uint32_t so = SWZ128((uint32_t)(r * 128 + c * 16));
            size_t ga = (size_t)(bm + r) * Dd + k0 + c * 8;
            size_t gb = (size_t)(bn + r) * Dd + k0 + c * 8;
            *(uint4*)(sAh + so) = *(const uint4*)(Ah + ga);
            *(uint4*)(sAl + so) = *(const uint4*)(Al + ga);
            *(uint4*)(sBh + so) = *(const uint4*)(Bh + gb);
            *(uint4*)(sBl + so) = *(const uint4*)(Bl + gb);
        }
        __syncthreads();
        warp_mma_3<4, 4>(C, aAh, aAl, aBh, aBl, wm0, wn0, lane);
        __syncthreads();
    }

    const int m0 = bm + wm0, n0 = bn + wn0;
    #pragma unroll
    for (int m = 0; m < 4; ++m)
        #pragma unroll
        for (int n = 0; n < 4; ++n) {
            #pragma unroll
            for (int e = 0; e < 4; ++e) {
                int mm = m0 + m * 16 + (lane >> 2) + ((e >> 1) << 3);
                int nn = n0 + n * 8 + ((lane & 3) << 1) + (e & 1);
                float val = C[m][n][e] + bias[nn];
                if (MODE == 0) {
                    outf[(size_t)mm * Dd + nn] = val;
                } else {
                    const int bb = mm >> 11, ss = mm & 2047, h = nn >> 6, d = nn & 63;
                    size_t o = ((size_t)(bb * Hh + h) * HDd + d) * Ss + ss;
                    split2h(val, oh[o], ol[o]);
                }
            }
        }
}

// ---------------------------------------------------------------------------
// qk1: per (b,h) scores = q @ k^T + mask -> fp16 scores (single term)
// ---------------------------------------------------------------------------
__global__ __launch_bounds__(256) void qk1_mma(
    const __half* __restrict__ qm, const __half* __restrict__ km,
    const float* __restrict__ amask, const unsigned char* __restrict__ kpm,
    __half* __restrict__ sc)
{
    extern __shared__ char smem[];
    char* sQ = smem;
    char* sK = smem + 16384;
    const uint32_t aQ = smem_u32(sQ), aK = smem_u32(sK);

    const int tid = threadIdx.x, lane = tid & 31, wid = tid >> 5;
    const int bn = blockIdx.x * 128, bm = blockIdx.y * 128, bh = blockIdx.z;
    const int bb = bh >> 4;

    const __half* Q = qm + (size_t)bh * Ss * HDd;
    const __half* K = km + (size_t)bh * Ss * HDd;

    #pragma unroll
    for (int p = 0; p < 4; ++p) {
        int u = tid + (p << 8);
        int r = u >> 3, c = u & 7;
        uint32_t so = SWZ128((uint32_t)(r * 128 + c * 16));
        *(uint4*)(sQ + so) = *(const uint4*)(Q + (size_t)(bm + r) * HDd + c * 8);
        *(uint4*)(sK + so) = *(const uint4*)(K + (size_t)(bn + r) * HDd + c * 8);
    }
    __syncthreads();

    float C[4][4][4] = {};
    warp_mma_1<4, 4>(C, aQ, aK, (wid >> 2) * 64, (wid & 3) * 32, lane);

    const int m0 = bm + (wid >> 2) * 64, n0 = bn + (wid & 3) * 32;
    #pragma unroll
    for (int m = 0; m < 4; ++m)
        #pragma unroll
        for (int n = 0; n < 4; ++n) {
            int qi0 = m0 + m * 16 + (lane >> 2);
            int kj  = n0 + n * 8 + ((lane & 3) << 1);
            bool p0 = kpm[bb * Ss + kj], p1 = kpm[bb * Ss + kj + 1];
            #pragma unroll
            for (int hf = 0; hf < 2; ++hf) {
                int qi = qi0 + hf * 8;
                float2 mk = *(const float2*)(amask + (size_t)qi * Ss + kj);
                float vx = C[m][n][hf * 2 + 0] + mk.x;
                float vy = C[m][n][hf * 2 + 1] + mk.y;
                if (p0) vx = -30000.0f;   // fp16-safe "-inf": exp -> 0
                if (p1) vy = -30000.0f;
                __half2 hv = __floats2half2_rn(vx, vy);
                *(__half2*)(sc + ((size_t)bh * Ss + qi) * Ss + kj) = hv;
            }
        }
}

// ---------------------------------------------------------------------------
// Fused softmax + head average, latency-optimized:
//  - thread t owns elements [8t, 8t+8) -> one uint4 load/store per head
//  - no max pass (scores bounded; masked = -30000 -> exp underflows to 0)
//  - prefetch next head's row while reducing the current one
// ---------------------------------------------------------------------------
__global__ __launch_bounds__(256) void softmax_avg(const __half* __restrict__ sc,
                                                   __half* __restrict__ pr,
                                                   float* __restrict__ avg)
{
    const int bi = blockIdx.x;
    const int b = bi >> 11, i = bi & 2047;
    const int t = threadIdx.x, lane = t & 31, w = t >> 5;
    __shared__ float sred[8];
    float acc[8] = {0, 0, 0, 0, 0, 0, 0, 0};

    // preload head 0
    uint4 raw = *(const uint4*)(sc + ((size_t)(b * Hh) * Ss + i) * Ss + t * 8);

    for (int h = 0; h < Hh; ++h) {
        const size_t ro = ((size_t)(b * Hh + h) * Ss + i) * Ss;
        // unpack current row chunk
        float v[8];
        {
            const __half2* p2 = reinterpret_cast<const __half2*>(&raw);
            #pragma unroll
            for (int j = 0; j < 4; ++j) {
                float2 f = __half22float2(p2[j]);
                v[2 * j] = f.x; v[2 * j + 1] = f.y;
            }
        }
        // prefetch next head (overlaps with the reduction below)
        if (h + 1 < Hh)
            raw = *(const uint4*)(sc + ((size_t)(b * Hh + h + 1) * Ss + i) * Ss + t * 8);

        float s = 0.0f;
        #pragma unroll
        for (int j = 0; j < 8; ++j) { v[j] = __expf(v[j]); s += v[j]; }
        #pragma unroll
        for (int o = 16; o; o >>= 1) s += __shfl_xor_sync(0xffffffffu, s, o);
        if (lane == 0) sred[w] = s;
        __syncthreads();
        float tot = sred[0] + sred[1] + sred[2] + sred[3]
                  + sred[4] + sred[5] + sred[6] + sred[7];
        __syncthreads();   // protect sred before next head's writes
        float inv = 1.0f / tot;

        uint4 outp;
        __half2* o2 = reinterpret_cast<__half2*>(&outp);
        #pragma unroll
        for (int j = 0; j < 4; ++j) {
            float p0 = v[2 * j] * inv, p1 = v[2 * j + 1] * inv;
            acc[2 * j] += p0; acc[2 * j + 1] += p1;
            o2[j] = __floats2half2_rn(p0, p1);
        }
        *(uint4*)(pr + ro + t * 8) = outp;
    }

    const float cinv = 1.0f / Hh;
    float* dst = avg + (size_t)bi * Ss + t * 8;
    float4 a0 = {acc[0] * cinv, acc[1] * cinv, acc[2] * cinv, acc[3] * cinv};
    float4 a1 = {acc[4] * cinv, acc[5] * cinv, acc[6] * cinv, acc[7] * cinv};
    *(float4*)(dst)     = a0;
    *(float4*)(dst + 4) = a1;
}

// ---------------------------------------------------------------------------
// pv2: per (b,h) attn = P @ (vh+vl); gate; emit ao dual fp16.
// Block 128x64, BK=64, 8 warps (4m x 2n), warp tile 32x32.
// ---------------------------------------------------------------------------
__global__ __launch_bounds__(256) void pv2_mma(
    const __half* __restrict__ pm,
    const __half* __restrict__ vth, const __half* __restrict__ vtl,
    const float* __restrict__ gate,
    __half* __restrict__ aoh, __half* __restrict__ aol)
{
    extern __shared__ char smem[];
    char* sP  = smem;
    char* sVh = smem + 16384;
    char* sVl = smem + 24576;
    const uint32_t aP = smem_u32(sP), aVh = smem_u32(sVh), aVl = smem_u32(sVl);

    const int tid = threadIdx.x, lane = tid & 31, wid = tid >> 5;
    const int bm = blockIdx.x * 128, bh = blockIdx.y;
    const int bb = bh >> 4, hh = bh & 15;

    const __half* P  = pm  + (size_t)bh * Ss * Ss;
    const __half* Vh = vth + (size_t)bh * HDd * Ss;
    const __half* Vl = vtl + (size_t)bh * HDd * Ss;

    float C[2][4][4] = {};
    const int wm0 = (wid >> 1) * 32, wn0 = (wid & 1) * 32;

    for (int k0 = 0; k0 < Ss; k0 += 64) {
        #pragma unroll
        for (int p = 0; p < 4; ++p) {
            int u = tid + (p << 8);
            int r = u >> 3, c = u & 7;
            uint32_t so = SWZ128((uint32_t)(r * 128 + c * 16));
            *(uint4*)(sP + so) = *(const uint4*)(P + (size_t)(bm + r) * Ss + k0 + c * 8);
        }
        #pragma unroll
        for (int p = 0; p < 2; ++p) {
            int u = tid + (p << 8);
            int r = u >> 3, c = u & 7;
            uint32_t so = SWZ128((uint32_t)(r * 128 + c * 16));
            size_t gv = (size_t)r * Ss + k0 + c * 8;
            *(uint4*)(sVh + so) = *(const uint4*)(Vh + gv);
            *(uint4*)(sVl + so) = *(const uint4*)(Vl + gv);
        }
        __syncthreads();
        warp_mma_1A2B<2, 4>(C, aP, aVh, aVl, wm0, wn0, lane);
        __syncthreads();
    }

    #pragma unroll
    for (int m = 0; m < 2; ++m)
        #pragma unroll
        for (int n = 0; n < 4; ++n) {
            int s0 = bm + wm0 + m * 16 + (lane >> 2);
            int d  = wn0 + n * 8 + ((lane & 3) << 1);
            #pragma unroll
            for (int q = 0; q < 2; ++q) {
                int s = s0 + q * 8;
                const float* grow = gate + ((size_t)bh * Ss + s) * HDd;
                __half* doh = aoh + (size_t)(bb * Ss + s) * Dd + hh * HDd;
                __half* dol = aol + (size_t)(bb * Ss + s) * Dd + hh * HDd;
                float v0 = C[m][n][q * 2 + 0] * grow[d];
                float v1 = C[m][n][q * 2 + 1] * grow[d + 1];
                split2h(v0, doh[d], dol[d]);
                split2h(v1, doh[d + 1], dol[d + 1]);
            }
        }
}

// ---------------------------------------------------------------------------
extern "C" void kernel_launch(void* const* d_in, const int* in_sizes, int n_in,
                              void* d_out, int out_size)
{
    const float*         x     = (const float*)d_in[0];
    const float*         amask = (const float*)d_in[1];
    const unsigned char* kpm   = (const unsigned char*)d_in[2];
    const float* Wq = (const float*)d_in[3];  const float* bq = (const float*)d_in[4];
    const float* Wk = (const float*)d_in[5];  const float* bk = (const float*)d_in[6];
    const float* Wv = (const float*)d_in[7];  const float* bv = (const float*)d_in[8];
    const float* Wg = (const float*)d_in[9];  const float* bg = (const float*)d_in[10];
    const float* Wo = (const float*)d_in[11]; const float* bo = (const float*)d_in[12];

    float* out = (float*)d_out;

    __half *xh, *xl, *wq, *wk, *wg, *wvh, *wvl, *woh, *wol;
    __half *q, *k, *vth, *vtl, *pr, *aoh, *aol, *sc;
    float *gate;
    cudaGetSymbolAddress((void**)&xh,  g_xh);  cudaGetSymbolAddress((void**)&xl,  g_xl);
    cudaGetSymbolAddress((void**)&wq,  g_wq);  cudaGetSymbolAddress((void**)&wk,  g_wk);
    cudaGetSymbolAddress((void**)&wg,  g_wg);
    cudaGetSymbolAddress((void**)&wvh, g_wvh); cudaGetSymbolAddress((void**)&wvl, g_wvl);
    cudaGetSymbolAddress((void**)&woh, g_woh); cudaGetSymbolAddress((void**)&wol, g_wol);
    cudaGetSymbolAddress((void**)&q,   g_q);   cudaGetSymbolAddress((void**)&k,   g_k);
    cudaGetSymbolAddress((void**)&vth, g_vth); cudaGetSymbolAddress((void**)&vtl, g_vtl);
    cudaGetSymbolAddress((void**)&gate, g_gate);
    cudaGetSymbolAddress((void**)&sc,  g_sc);
    cudaGetSymbolAddress((void**)&pr,  g_p);
    cudaGetSymbolAddress((void**)&aoh, g_aoh); cudaGetSymbolAddress((void**)&aol, g_aol);

    const int SM_P2 = 49152;   // proj2: 3 x 16 KB
    const int SM_P3 = 65536;   // proj3: 4 x 16 KB
    const int SM_QK = 32768;   // qk1:   2 x 16 KB
    const int SM_PV = 32768;   // pv2:   16 + 8 + 8 KB
    cudaFuncSetAttribute(proj2_mma<1>, cudaFuncAttributeMaxDynamicSharedMemorySize, SM_P2);
    cudaFuncSetAttribute(proj2_mma<2>, cudaFuncAttributeMaxDynamicSharedMemorySize, SM_P2);
    cudaFuncSetAttribute(proj2_mma<3>, cudaFuncAttributeMaxDynamicSharedMemorySize, SM_P2);
    cudaFuncSetAttribute(proj3_mma<0>, cudaFuncAttributeMaxDynamicSharedMemorySize, SM_P3);
    cudaFuncSetAttribute(proj3_mma<4>, cudaFuncAttributeMaxDynamicSharedMemorySize, SM_P3);
    cudaFuncSetAttribute(qk1_mma,      cudaFuncAttributeMaxDynamicSharedMemorySize, SM_QK);
    cudaFuncSetAttribute(pv2_mma,      cudaFuncAttributeMaxDynamicSharedMemorySize, SM_PV);

    // 1. conversions
    split_f16<<<2048, 256>>>(x, xh, xl, BSZ * Dd);
    wt_1<<<dim3(32, 32), dim3(32, 8)>>>(Wq, wq);
    wt_1<<<dim3(32, 32), dim3(32, 8)>>>(Wk, wk);
    wt_1<<<dim3(32, 32), dim3(32, 8)>>>(Wg, wg);
    wt_2<<<dim3(32, 32), dim3(32, 8)>>>(Wv, wvh, wvl);
    wt_2<<<dim3(32, 32), dim3(32, 8)>>>(Wo, woh, wol);

    // 2. projections
    dim3 pg(8, 32);
    proj2_mma<2><<<pg, 256, SM_P2>>>(xh, xl, wq, bq, nullptr, q);     // q (pre-scaled)
    proj2_mma<1><<<pg, 256, SM_P2>>>(xh, xl, wk, bk, nullptr, k);     // k
    proj2_mma<3><<<pg, 256, SM_P2>>>(xh, xl, wg, bg, gate, nullptr);  // gate
    proj3_mma<4><<<pg, 256, SM_P3>>>(xh, xl, wvh, wvl, bv, nullptr, vth, vtl); // v dual

    // 3. attention
    qk1_mma<<<dim3(16, 16, 32), 256, SM_QK>>>(q, k, amask, kpm, sc);
    softmax_avg<<<BSZ, 256>>>(sc, pr, out + (size_t)BSZ * Dd);
    pv2_mma<<<dim3(16, 32), 256, SM_PV>>>(pr, vth, vtl, gate, aoh, aol);

    // 4. output projection (full precision: 3-term)
    proj3_mma<0><<<pg, 256, SM_P3>>>(aoh, aol, woh, wol, bo, out, nullptr, nullptr);
}

// round 14
// speedup vs baseline: 3.3507x; 1.0862x over previous
#include <cuda_runtime.h>
#include <cuda_fp16.h>
#include <cstdint>

#define Bb   2
#define Ss   2048
#define Dd   1024
#define Hh   16
#define HDd  64
#define BHh  32
#define BSZ  4096

// ------------------------------ scratch ------------------------------------
__device__ __half g_xh[BSZ * Dd], g_xl[BSZ * Dd];                    // x dual fp16
__device__ __half g_wq[Dd * Dd], g_wk[Dd * Dd], g_wg[Dd * Dd];       // W^T single
__device__ __half g_wv[Dd * Dd], g_wo[Dd * Dd];                      // W^T single
__device__ __half g_q[BHh * Ss * HDd], g_k[BHh * Ss * HDd];          // single, head-major
__device__ __half g_vt[BHh * HDd * Ss];                              // v^T single [bh][d][s]
__device__ float  g_gate[BHh * Ss * HDd];
__device__ __half g_sc[(size_t)BHh * Ss * Ss];                       // scores fp16
__device__ __half g_p[(size_t)BHh * Ss * Ss];                        // probs single fp16
__device__ __half g_aoh[BSZ * Dd], g_aol[BSZ * Dd];                  // ao dual

// --------------------------- helpers ---------------------------------------
__device__ __forceinline__ uint32_t smem_u32(const void* p) {
    uint32_t a;
    asm("{ .reg .u64 t; cvta.to.shared.u64 t, %1; cvt.u32.u64 %0, t; }" : "=r"(a) : "l"(p));
    return a;
}
#define SWZ128(o) ((o) ^ (((o) >> 3) & 0x70))

__device__ __forceinline__ void ldsm4(uint32_t r[4], uint32_t addr) {
    asm volatile("ldmatrix.sync.aligned.m8n8.x4.shared.b16 {%0,%1,%2,%3}, [%4];"
                 : "=r"(r[0]), "=r"(r[1]), "=r"(r[2]), "=r"(r[3]) : "r"(addr));
}
__device__ __forceinline__ void mma16816(float c[4], const uint32_t a[4], const uint32_t b[2]) {
    asm volatile("mma.sync.aligned.m16n8k16.row.col.f32.f16.f16.f32 "
                 "{%0,%1,%2,%3}, {%4,%5,%6,%7}, {%8,%9}, {%0,%1,%2,%3};"
                 : "+f"(c[0]), "+f"(c[1]), "+f"(c[2]), "+f"(c[3])
                 : "r"(a[0]), "r"(a[1]), "r"(a[2]), "r"(a[3]), "r"(b[0]), "r"(b[1]));
}
__device__ __forceinline__ void split2h(float x, __half& h, __half& l) {
    h = __float2half_rn(x);
    l = __float2half_rn(x - __half2float(h));
}

// B-fragment loader: WN x (2 halves of k64) x4regs from a tile at (n0 rows)
#define LOAD_BFRAG(dst, abase) \
    _Pragma("unroll") \
    for (int n = 0; n < WN; ++n) \
        _Pragma("unroll") \
        for (int hf = 0; hf < 2; ++hf) { \
            uint32_t off = SWZ128((uint32_t)((n0 + n * 8 + (lane & 7)) * 128 + hf * 64 + ((lane >> 3) << 4))); \
            ldsm4((dst)[n][hf], (abase) + off); \
        }

#define AFRAG_OFF(m) \
    SWZ128((uint32_t)((m0 + (m) * 16 + (lane & 7) + (((lane >> 3) & 1) << 3)) * 128 + ks * 32 + ((lane >> 4) << 4)))

// 1 term: C += A*B
template<int WM, int WN>
__device__ __forceinline__ void warp_mma_1(
    float (&C)[WM][WN][4], uint32_t aA, uint32_t aB, int m0, int n0, int lane)
{
    uint32_t Bf[WN][2][4];
    LOAD_BFRAG(Bf, aB)
    #pragma unroll
    for (int ks = 0; ks < 4; ++ks) {
        uint32_t Af[WM][4];
        #pragma unroll
        for (int m = 0; m < WM; ++m) ldsm4(Af[m], aA + AFRAG_OFF(m));
        #pragma unroll
        for (int m = 0; m < WM; ++m)
            #pragma unroll
            for (int n = 0; n < WN; ++n)
                mma16816(C[m][n], Af[m], &Bf[n][ks >> 1][(ks & 1) << 1]);
    }
}

// 2 terms sharing B: C += A0*B + A1*B
template<int WM, int WN>
__device__ __forceinline__ void warp_mma_2A1B(
    float (&C)[WM][WN][4], uint32_t aA0, uint32_t aA1, uint32_t aB, int m0, int n0, int lane)
{
    uint32_t Bf[WN][2][4];
    LOAD_BFRAG(Bf, aB)
    #pragma unroll
    for (int ks = 0; ks < 4; ++ks) {
        uint32_t A0[WM][4], A1[WM][4];
        #pragma unroll
        for (int m = 0; m < WM; ++m) { ldsm4(A0[m], aA0 + AFRAG_OFF(m)); ldsm4(A1[m], aA1 + AFRAG_OFF(m)); }
        #pragma unroll
        for (int m = 0; m < WM; ++m)
            #pragma unroll
            for (int n = 0; n < WN; ++n) {
                const uint32_t* b = &Bf[n][ks >> 1][(ks & 1) << 1];
                mma16816(C[m][n], A0[m], b);
                mma16816(C[m][n], A1[m], b);
            }
    }
}

// -------------------- conversion kernels -----------------------------------
__global__ __launch_bounds__(256) void split_f16(const float* __restrict__ in,
                                                 __half* __restrict__ hi,
                                                 __half* __restrict__ lo, int n) {
    for (int i = blockIdx.x * 256 + threadIdx.x; i < n; i += gridDim.x * 256)
        split2h(in[i], hi[i], lo[i]);
}

// W [K,N] row-major -> Wt[n][k], single fp16
__global__ __launch_bounds__(256) void wt_1(const float* __restrict__ W, __half* __restrict__ t1) {
    __shared__ float t[32][33];
    const int tx = threadIdx.x, ty = threadIdx.y;
    const int n0 = blockIdx.x * 32, k0 = blockIdx.y * 32;
    #pragma unroll
    for (int i = 0; i < 4; ++i)
        t[ty + 8 * i][tx] = W[(size_t)(k0 + ty + 8 * i) * Dd + n0 + tx];
    __syncthreads();
    #pragma unroll
    for (int i = 0; i < 4; ++i)
        t1[(size_t)(n0 + ty + 8 * i) * Dd + k0 + tx] = __float2half_rn(t[tx][ty + 8 * i]);
}

// ---------------------------------------------------------------------------
// proj2: C(4096,1024) = (Ah+Al) @ B^T + bias, 2 terms (A dual, B single).
// MODE: 0 fp32 row-major out (output proj);
//       1 k single head-major; 2 q single head-major *0.125;
//       3 gate sigmoid fp32 head-major; 4 v single transposed [bh][d][s]
// ---------------------------------------------------------------------------
template<int MODE>
__global__ __launch_bounds__(256) void proj2_mma(
    const __half* __restrict__ Ah, const __half* __restrict__ Al,
    const __half* __restrict__ Bw, const float* __restrict__ bias,
    float* __restrict__ outf, __half* __restrict__ oh)
{
    extern __shared__ char smem[];
    char* sAh = smem;
    char* sAl = smem + 16384;
    char* sBw = smem + 32768;
    const uint32_t aAh = smem_u32(sAh), aAl = smem_u32(sAl), aBw = smem_u32(sBw);

    const int tid = threadIdx.x, lane = tid & 31, wid = tid >> 5;
    const int bm = blockIdx.y * 128, bn = blockIdx.x * 128;
    const int wm0 = (wid >> 2) * 64, wn0 = (wid & 3) * 32;

    float C[4][4][4] = {};

    for (int k0 = 0; k0 < Dd; k0 += 64) {
        #pragma unroll
        for (int p = 0; p < 4; ++p) {
            int u = tid + (p << 8);
            int r = u >> 3, c = u & 7;
            uint32_t so = SWZ128((uint32_t)(r * 128 + c * 16));
            size_t ga = (size_t)(bm + r) * Dd + k0 + c * 8;
            size_t gb = (size_t)(bn + r) * Dd + k0 + c * 8;
            *(uint4*)(sAh + so) = *(const uint4*)(Ah + ga);
            *(uint4*)(sAl + so) = *(const uint4*)(Al + ga);
            *(uint4*)(sBw + so) = *(const uint4*)(Bw + gb);
        }
        __syncthreads();
        warp_mma_2A1B<4, 4>(C, aAh, aAl, aBw, wm0, wn0, lane);
        __syncthreads();
    }

    const int m0 = bm + wm0, n0 = bn + wn0;
    #pragma unroll
    for (int m = 0; m < 4; ++m)
        #pragma unroll
        for (int n = 0; n < 4; ++n) {
            #pragma unroll
            for (int e = 0; e < 4; ++e) {
                int mm = m0 + m * 16 + (lane >> 2) + ((e >> 1) << 3);
                int nn = n0 + n * 8 + ((lane & 3) << 1) + (e & 1);
                float val = C[m][n][e] + bias[nn];
                if (MODE == 0) {
                    outf[(size_t)mm * Dd + nn] = val;
                } else {
                    const int bb = mm >> 11, ss = mm & 2047, h = nn >> 6, d = nn & 63;
                    if (MODE == 2)
                        oh[((size_t)(bb * Hh + h) * Ss + ss) * HDd + d] = __float2half_rn(val * 0.125f);
                    else if (MODE == 1)
                        oh[((size_t)(bb * Hh + h) * Ss + ss) * HDd + d] = __float2half_rn(val);
                    else if (MODE == 3)
                        outf[((size_t)(bb * Hh + h) * Ss + ss) * HDd + d] = 1.0f / (1.0f + __expf(-val));
                    else // MODE 4: v single, transposed
                        oh[((size_t)(bb * Hh + h) * HDd + d) * Ss + ss] = __float2half_rn(val);
                }
            }
        }
}

// ---------------------------------------------------------------------------
// qk1: per (b,h) scores = q @ k^T + mask -> fp16 scores (single term)
// ---------------------------------------------------------------------------
__global__ __launch_bounds__(256) void qk1_mma(
    const __half* __restrict__ qm, const __half* __restrict__ km,
    const float* __restrict__ amask, const unsigned char* __restrict__ kpm,
    __half* __restrict__ sc)
{
    extern __shared__ char smem[];
    char* sQ = smem;
    char* sK = smem + 16384;
    const uint32_t aQ = smem_u32(sQ), aK = smem_u32(sK);

    const int tid = threadIdx.x, lane = tid & 31, wid = tid >> 5;
    const int bn = blockIdx.x * 128, bm = blockIdx.y * 128, bh = blockIdx.z;
    const int bb = bh >> 4;

    const __half* Q = qm + (size_t)bh * Ss * HDd;
    const __half* K = km + (size_t)bh * Ss * HDd;

    #pragma unroll
    for (int p = 0; p < 4; ++p) {
        int u = tid + (p << 8);
        int r = u >> 3, c = u & 7;
        uint32_t so = SWZ128((uint32_t)(r * 128 + c * 16));
        *(uint4*)(sQ + so) = *(const uint4*)(Q + (size_t)(bm + r) * HDd + c * 8);
        *(uint4*)(sK + so) = *(const uint4*)(K + (size_t)(bn + r) * HDd + c * 8);
    }
    __syncthreads();

    float C[4][4][4] = {};
    warp_mma_1<4, 4>(C, aQ, aK, (wid >> 2) * 64, (wid & 3) * 32, lane);

    const int m0 = bm + (wid >> 2) * 64, n0 = bn + (wid & 3) * 32;
    #pragma unroll
    for (int m = 0; m < 4; ++m)
        #pragma unroll
        for (int n = 0; n < 4; ++n) {
            int qi0 = m0 + m * 16 + (lane >> 2);
            int kj  = n0 + n * 8 + ((lane & 3) << 1);
            bool p0 = kpm[bb * Ss + kj], p1 = kpm[bb * Ss + kj + 1];
            #pragma unroll
            for (int hf = 0; hf < 2; ++hf) {
                int qi = qi0 + hf * 8;
                float2 mk = *(const float2*)(amask + (size_t)qi * Ss + kj);
                float vx = C[m][n][hf * 2 + 0] + mk.x;
                float vy = C[m][n][hf * 2 + 1] + mk.y;
                if (p0) vx = -30000.0f;   // fp16-safe "-inf": exp -> 0
                if (p1) vy = -30000.0f;
                __half2 hv = __floats2half2_rn(vx, vy);
                *(__half2*)(sc + ((size_t)bh * Ss + qi) * Ss + kj) = hv;
            }
        }
}

// ---------------------------------------------------------------------------
// Fused softmax + head average, latency-optimized (uint4 per head, no max pass,
// next-head prefetch).
// ---------------------------------------------------------------------------
__global__ __launch_bounds__(256) void softmax_avg(const __half* __restrict__ sc,
                                                   __half* __restrict__ pr,
                                                   float* __restrict__ avg)
{
    const int bi = blockIdx.x;
    const int b = bi >> 11, i = bi & 2047;
    const int t = threadIdx.x, lane = t & 31, w = t >> 5;
    __shared__ float sred[8];
    float acc[8] = {0, 0, 0, 0, 0, 0, 0, 0};

    uint4 raw = *(const uint4*)(sc + ((size_t)(b * Hh) * Ss + i) * Ss + t * 8);

    for (int h = 0; h < Hh; ++h) {
        const size_t ro = ((size_t)(b * Hh + h) * Ss + i) * Ss;
        float v[8];
        {
            const __half2* p2 = reinterpret_cast<const __half2*>(&raw);
            #pragma unroll
            for (int j = 0; j < 4; ++j) {
                float2 f = __half22float2(p2[j]);
                v[2 * j] = f.x; v[2 * j + 1] = f.y;
            }
        }
        if (h + 1 < Hh)
            raw = *(const uint4*)(sc + ((size_t)(b * Hh + h + 1) * Ss + i) * Ss + t * 8);

        float s = 0.0f;
        #pragma unroll
        for (int j = 0; j < 8; ++j) { v[j] = __expf(v[j]); s += v[j]; }
        #pragma unroll
        for (int o = 16; o; o >>= 1) s += __shfl_xor_sync(0xffffffffu, s, o);
        if (lane == 0) sred[w] = s;
        __syncthreads();
        float tot = sred[0] + sred[1] + sred[2] + sred[3]
                  + sred[4] + sred[5] + sred[6] + sred[7];
        __syncthreads();
        float inv = 1.0f / tot;

        uint4 outp;
        __half2* o2 = reinterpret_cast<__half2*>(&outp);
        #pragma unroll
        for (int j = 0; j < 4; ++j) {
            float p0 = v[2 * j] * inv, p1 = v[2 * j + 1] * inv;
            acc[2 * j] += p0; acc[2 * j + 1] += p1;
            o2[j] = __floats2half2_rn(p0, p1);
        }
        *(uint4*)(pr + ro + t * 8) = outp;
    }

    const float cinv = 1.0f / Hh;
    float* dst = avg + (size_t)bi * Ss + t * 8;
    float4 a0 = {acc[0] * cinv, acc[1] * cinv, acc[2] * cinv, acc[3] * cinv};
    float4 a1 = {acc[4] * cinv, acc[5] * cinv, acc[6] * cinv, acc[7] * cinv};
    *(float4*)(dst)     = a0;
    *(float4*)(dst + 4) = a1;
}

// ---------------------------------------------------------------------------
// pv1: per (b,h) attn = P @ v (both single fp16, 1 term); gate; ao dual.
// Block 128x64, BK=64, 8 warps (4m x 2n), warp tile 32x32.
// ---------------------------------------------------------------------------
__global__ __launch_bounds__(256) void pv1_mma(
    const __half* __restrict__ pm, const __half* __restrict__ vt,
    const float* __restrict__ gate,
    __half* __restrict__ aoh, __half* __restrict__ aol)
{
    extern __shared__ char smem[];
    char* sP = smem;
    char* sV = smem + 16384;
    const uint32_t aP = smem_u32(sP), aV = smem_u32(sV);

    const int tid = threadIdx.x, lane = tid & 31, wid = tid >> 5;
    const int bm = blockIdx.x * 128, bh = blockIdx.y;
    const int bb = bh >> 4, hh = bh & 15;

    const __half* P = pm + (size_t)bh * Ss * Ss;
    const __half* V = vt + (size_t)bh * HDd * Ss;

    float C[2][4][4] = {};
    const int wm0 = (wid >> 1) * 32, wn0 = (wid & 1) * 32;

    for (int k0 = 0; k0 < Ss; k0 += 64) {
        #pragma unroll
        for (int p = 0; p < 4; ++p) {
            int u = tid + (p << 8);
            int r = u >> 3, c = u & 7;
            uint32_t so = SWZ128((uint32_t)(r * 128 + c * 16));
            *(uint4*)(sP + so) = *(const uint4*)(P + (size_t)(bm + r) * Ss + k0 + c * 8);
        }
        {
            int u = tid;
            int r = u >> 3, c = u & 7;
            uint32_t so = SWZ128((uint32_t)(r * 128 + c * 16));
            *(uint4*)(sV + so) = *(const uint4*)(V + (size_t)r * Ss + k0 + c * 8);
        }
        {
            int u = tid + 256;
            int r = u >> 3, c = u & 7;
            uint32_t so = SWZ128((uint32_t)(r * 128 + c * 16));
            *(uint4*)(sV + so) = *(const uint4*)(V + (size_t)r * Ss + k0 + c * 8);
        }
        __syncthreads();
        warp_mma_1<2, 4>(C, aP, aV, wm0, wn0, lane);
        __syncthreads();
    }

    #pragma unroll
    for (int m = 0; m < 2; ++m)
        #pragma unroll
        for (int n = 0; n < 4; ++n) {
            int s0 = bm + wm0 + m * 16 + (lane >> 2);
            int d  = wn0 + n * 8 + ((lane & 3) << 1);
            #pragma unroll
            for (int q = 0; q < 2; ++q) {
                int s = s0 + q * 8;
                const float* grow = gate + ((size_t)bh * Ss + s) * HDd;
                __half* doh = aoh + (size_t)(bb * Ss + s) * Dd + hh * HDd;
                __half* dol = aol + (size_t)(bb * Ss + s) * Dd + hh * HDd;
                float v0 = C[m][n][q * 2 + 0] * grow[d];
                float v1 = C[m][n][q * 2 + 1] * grow[d + 1];
                split2h(v0, doh[d], dol[d]);
                split2h(v1, doh[d + 1], dol[d + 1]);
            }
        }
}

// ---------------------------------------------------------------------------
extern "C" void kernel_launch(void* const* d_in, const int* in_sizes, int n_in,
                              void* d_out, int out_size)
{
    const float*         x     = (const float*)d_in[0];
    const float*         amask = (const float*)d_in[1];
    const unsigned char* kpm   = (const unsigned char*)d_in[2];
    const float* Wq = (const float*)d_in[3];  const float* bq = (const float*)d_in[4];
    const float* Wk = (const float*)d_in[5];  const float* bk = (const float*)d_in[6];
    const float* Wv = (const float*)d_in[7];  const float* bv = (const float*)d_in[8];
    const float* Wg = (const float*)d_in[9];  const float* bg = (const float*)d_in[10];
    const float* Wo = (const float*)d_in[11]; const float* bo = (const float*)d_in[12];

    float* out = (float*)d_out;

    __half *xh, *xl, *wq, *wk, *wg, *wv, *wo;
    __half *q, *k, *vt, *pr, *aoh, *aol, *sc;
    float *gate;
    cudaGetSymbolAddress((void**)&xh,  g_xh);  cudaGetSymbolAddress((void**)&xl,  g_xl);
    cudaGetSymbolAddress((void**)&wq,  g_wq);  cudaGetSymbolAddress((void**)&wk,  g_wk);
    cudaGetSymbolAddress((void**)&wg,  g_wg);
    cudaGetSymbolAddress((void**)&wv,  g_wv);  cudaGetSymbolAddress((void**)&wo,  g_wo);
    cudaGetSymbolAddress((void**)&q,   g_q);   cudaGetSymbolAddress((void**)&k,   g_k);
    cudaGetSymbolAddress((void**)&vt,  g_vt);
    cudaGetSymbolAddress((void**)&gate, g_gate);
    cudaGetSymbolAddress((void**)&sc,  g_sc);
    cudaGetSymbolAddress((void**)&pr,  g_p);
    cudaGetSymbolAddress((void**)&aoh, g_aoh); cudaGetSymbolAddress((void**)&aol, g_aol);

    const int SM_P2 = 49152;   // proj2: 3 x 16 KB
    const int SM_QK = 32768;   // qk1:   2 x 16 KB
    const int SM_PV = 24576;   // pv1:   16 + 8 KB
    cudaFuncSetAttribute(proj2_mma<0>, cudaFuncAttributeMaxDynamicSharedMemorySize, SM_P2);
    cudaFuncSetAttribute(proj2_mma<1>, cudaFuncAttributeMaxDynamicSharedMemorySize, SM_P2);
    cudaFuncSetAttribute(proj2_mma<2>, cudaFuncAttributeMaxDynamicSharedMemorySize, SM_P2);
    cudaFuncSetAttribute(proj2_mma<3>, cudaFuncAttributeMaxDynamicSharedMemorySize, SM_P2);
    cudaFuncSetAttribute(proj2_mma<4>, cudaFuncAttributeMaxDynamicSharedMemorySize, SM_P2);
    cudaFuncSetAttribute(qk1_mma,      cudaFuncAttributeMaxDynamicSharedMemorySize, SM_QK);
    cudaFuncSetAttribute(pv1_mma,      cudaFuncAttributeMaxDynamicSharedMemorySize, SM_PV);

    // 1. conversions
    split_f16<<<2048, 256>>>(x, xh, xl, BSZ * Dd);
    wt_1<<<dim3(32, 32), dim3(32, 8)>>>(Wq, wq);
    wt_1<<<dim3(32, 32), dim3(32, 8)>>>(Wk, wk);
    wt_1<<<dim3(32, 32), dim3(32, 8)>>>(Wg, wg);
    wt_1<<<dim3(32, 32), dim3(32, 8)>>>(Wv, wv);
    wt_1<<<dim3(32, 32), dim3(32, 8)>>>(Wo, wo);

    // 2. projections (all 2-term: x dual @ W single)
    dim3 pg(8, 32);
    proj2_mma<2><<<pg, 256, SM_P2>>>(xh, xl, wq, bq, nullptr, q);     // q (pre-scaled)
    proj2_mma<1><<<pg, 256, SM_P2>>>(xh, xl, wk, bk, nullptr, k);     // k
    proj2_mma<3><<<pg, 256, SM_P2>>>(xh, xl, wg, bg, gate, nullptr);  // gate
    proj2_mma<4><<<pg, 256, SM_P2>>>(xh, xl, wv, bv, nullptr, vt);    // v single, transposed

    // 3. attention
    qk1_mma<<<dim3(16, 16, 32), 256, SM_QK>>>(q, k, amask, kpm, sc);
    softmax_avg<<<BSZ, 256>>>(sc, pr, out + (size_t)BSZ * Dd);
    pv1_mma<<<dim3(16, 32), 256, SM_PV>>>(pr, vt, gate, aoh, aol);

    // 4. output projection (2-term: ao dual @ Wo single)
    proj2_mma<0><<<pg, 256, SM_P2>>>(aoh, aol, wo, bo, out, nullptr);
}